// round 10
// baseline (speedup 1.0000x reference)
#include <cuda_runtime.h>
#include <math.h>
#include <stdint.h>

#define EMB   768
#define DFF   3072
#define NTOK  16384
#define HEADS 12
#define HD    64
#define SEQ   1024
#define BATCH 16
#define QKV3  2304

// ---------------- scratch (no allocations allowed) ----------------
__device__ float g_h   [NTOK * EMB];
__device__ float g_qkv [NTOK * QKV3];
__device__ float g_ctx [NTOK * EMB];
__device__ float g_x1  [NTOK * EMB];
__device__ float g_h2  [NTOK * EMB];
__device__ float g_ff  [NTOK * DFF];
// pre-transposed + tf32-rounded weights
__device__ float g_wqkvT[QKV3 * EMB];
__device__ float g_woT  [EMB * EMB];
__device__ float g_w1T  [DFF * EMB];
__device__ float g_w2T  [EMB * DFF];
__device__ float g_bqkv [QKV3];

// ---------------- helpers ----------------
__device__ __forceinline__ float f2tf(float f) {
    unsigned u;
    asm("cvt.rna.tf32.f32 %0, %1;" : "=r"(u) : "f"(f));
    return __uint_as_float(u);
}

__device__ __forceinline__ void mma8(float* c, const unsigned* a, const unsigned* b) {
    asm volatile(
        "mma.sync.aligned.m16n8k8.row.col.f32.tf32.tf32.f32 "
        "{%0,%1,%2,%3}, {%4,%5,%6,%7}, {%8,%9}, {%0,%1,%2,%3};"
        : "+f"(c[0]), "+f"(c[1]), "+f"(c[2]), "+f"(c[3])
        : "r"(a[0]), "r"(a[1]), "r"(a[2]), "r"(a[3]), "r"(b[0]), "r"(b[1]));
}

__device__ __forceinline__ void ldsm4(unsigned& r0, unsigned& r1, unsigned& r2,
                                      unsigned& r3, uint32_t addr) {
    asm volatile("ldmatrix.sync.aligned.m8n8.x4.shared.b16 {%0,%1,%2,%3}, [%4];"
                 : "=r"(r0), "=r"(r1), "=r"(r2), "=r"(r3) : "r"(addr));
}

#define CP_ASYNC16(dst, src) \
    asm volatile("cp.async.cg.shared.global [%0], [%1], 16;" :: "r"(dst), "l"(src))
#define CP_COMMIT() asm volatile("cp.async.commit_group;")
#define CP_WAIT1()  asm volatile("cp.async.wait_group 1;")
#define CP_WAIT0()  asm volatile("cp.async.wait_group 0;")

__device__ __forceinline__ float block_reduce_sum(float v, float* red) {
    #pragma unroll
    for (int off = 16; off > 0; off >>= 1)
        v += __shfl_xor_sync(0xffffffffu, v, off);
    int w = threadIdx.x >> 5;
    if ((threadIdx.x & 31) == 0) red[w] = v;
    __syncthreads();
    if (threadIdx.x < 32) {
        float t = (threadIdx.x < 8) ? red[threadIdx.x] : 0.0f;
        #pragma unroll
        for (int off = 4; off > 0; off >>= 1)
            t += __shfl_xor_sync(0xffffffffu, t, off);
        if (threadIdx.x == 0) red[0] = t;
    }
    __syncthreads();
    float r = red[0];
    __syncthreads();
    return r;
}

// ---------------- prep: all 6 weight transposes in ONE launch ----------------
__global__ void __launch_bounds__(256) transpose_all(
    const float* __restrict__ Wq, const float* __restrict__ Wk,
    const float* __restrict__ Wv, const float* __restrict__ Wo,
    const float* __restrict__ W1, const float* __restrict__ W2)
{
    const float* src; float* dst; int K, N;
    switch (blockIdx.z) {
        case 0: src = Wq; dst = g_wqkvT;               K = EMB; N = EMB; break;
        case 1: src = Wk; dst = g_wqkvT + EMB * EMB;   K = EMB; N = EMB; break;
        case 2: src = Wv; dst = g_wqkvT + 2*EMB*EMB;   K = EMB; N = EMB; break;
        case 3: src = Wo; dst = g_woT;                 K = EMB; N = EMB; break;
        case 4: src = W1; dst = g_w1T;                 K = EMB; N = DFF; break;
        default:src = W2; dst = g_w2T;                 K = DFF; N = EMB; break;
    }
    const int n0 = blockIdx.x * 32;
    const int k0 = blockIdx.y * 32;
    if (n0 >= N || k0 >= K) return;

    __shared__ float t[32][33];
    const int tx = threadIdx.x & 31;
    const int ty = threadIdx.x >> 5;
    #pragma unroll
    for (int j = 0; j < 4; j++)
        t[ty + j * 8][tx] = src[(size_t)(k0 + ty + j * 8) * N + n0 + tx];
    __syncthreads();
    #pragma unroll
    for (int j = 0; j < 4; j++)
        dst[(size_t)(n0 + ty + j * 8) * K + k0 + tx] = f2tf(t[tx][ty + j * 8]);
}

__global__ void bias_concat(const float* bq, const float* bk, const float* bv,
                            float* out)
{
    int i = blockIdx.x * 256 + threadIdx.x;
    if (i < QKV3) {
        float v = (i < EMB) ? bq[i] : (i < 2 * EMB) ? bk[i - EMB] : bv[i - 2 * EMB];
        out[i] = v;
    }
}

// ---------------- LayerNorm (outputs tf32-rounded) ----------------
__global__ void __launch_bounds__(256) ln_kernel(
    const float* __restrict__ x, const float* __restrict__ gw,
    const float* __restrict__ bw, float* __restrict__ out)
{
    __shared__ float red[32];
    const int row = blockIdx.x;
    const float* xr = x + (size_t)row * EMB;

    float vals[3];
    float lsum = 0.0f;
    #pragma unroll
    for (int i = 0; i < 3; i++) {
        vals[i] = xr[threadIdx.x + i * 256];
        lsum += vals[i];
    }
    float mu = block_reduce_sum(lsum, red) * (1.0f / EMB);

    float ls2 = 0.0f;
    #pragma unroll
    for (int i = 0; i < 3; i++) {
        float d = vals[i] - mu;
        ls2 += d * d;
    }
    float var = block_reduce_sum(ls2, red) * (1.0f / EMB);
    float rs = rsqrtf(var + 1e-5f);

    float* outr = out + (size_t)row * EMB;
    #pragma unroll
    for (int i = 0; i < 3; i++) {
        int c = threadIdx.x + i * 256;
        outr[c] = f2tf((vals[i] - mu) * rs * gw[c] + bw[c]);
    }
}

// ---------------- fused flash attention (tf32 mma.sync; unchanged R4) --------
#define QP 68
#define VP 72
#define PP 132

__global__ void __launch_bounds__(256) flash_kernel(
    const float* __restrict__ qkv, float* __restrict__ ctx)
{
    extern __shared__ float fs[];
    const uint32_t base  = (uint32_t)__cvta_generic_to_shared(fs);
    const uint32_t kBase = base;
    const uint32_t vBase = kBase + 2u * 128 * QP * 4;
    float* Pfs = fs + 2 * 128 * QP + 2 * 128 * VP;

    const int tid  = threadIdx.x;
    const int w    = tid >> 5;
    const int lane = tid & 31;
    const int gi   = lane >> 2;
    const int li   = lane & 3;
    const int q0   = blockIdx.x * 128;
    const int z    = blockIdx.y;
    const int b    = z / HEADS, h = z % HEADS;

    const float* qptr = qkv + (size_t)(b * SEQ + q0) * QKV3 + h * HD;
    const float* kptr = qkv + (size_t)(b * SEQ) * QKV3 + EMB + h * HD;
    const float* vptr = qkv + (size_t)(b * SEQ) * QKV3 + 2 * EMB + h * HD;

    {
        uint32_t dst = vBase + 128u * VP * 4;
        #pragma unroll
        for (int i = 0; i < 8; i++) {
            int idx = tid + i * 256;
            int r = idx >> 4, c = (idx & 15) * 4;
            CP_ASYNC16(dst + (uint32_t)(r * QP + c) * 4, qptr + (size_t)r * QKV3 + c);
        }
    }
    CP_COMMIT();
    CP_WAIT0();
    __syncthreads();

    unsigned qf[8][4];
    {
        uint32_t qb = vBase + 128u * VP * 4;
        int rowA = w * 16 + (lane & 15);
        int kqA  = (lane >> 4) * 4;
        #pragma unroll
        for (int ks = 0; ks < 8; ks++)
            ldsm4(qf[ks][0], qf[ks][1], qf[ks][2], qf[ks][3],
                  qb + (uint32_t)(rowA * QP + ks * 8 + kqA) * 4);
    }
    __syncthreads();

    float m0 = -1e30f, m1 = -1e30f, l0 = 0.0f, l1 = 0.0f;
    float O[8][4];
    #pragma unroll
    for (int nt = 0; nt < 8; nt++)
        #pragma unroll
        for (int t = 0; t < 4; t++) O[nt][t] = 0.0f;

    const int rowB = ((lane >> 4) & 1) * 8 + (lane & 7);
    const int kqB  = ((lane >> 3) & 1) * 4;
    const int prow0 = w * 16 + gi;
    const int prow1 = prow0 + 8;

    {
        #pragma unroll
        for (int i = 0; i < 8; i++) {
            int idx = tid + i * 256;
            int r = idx >> 4, c = (idx & 15) * 4;
            CP_ASYNC16(kBase + (uint32_t)(r * QP + c) * 4, kptr + (size_t)r * QKV3 + c);
            CP_ASYNC16(vBase + (uint32_t)(r * VP + c) * 4, vptr + (size_t)r * QKV3 + c);
        }
        CP_COMMIT();
    }

    for (int t = 0; t < 8; t++) {
        const int st = t & 1;
        if (t < 7) {
            const int ns = st ^ 1;
            const float* kp = kptr + (size_t)(t + 1) * 128 * QKV3;
            const float* vp = vptr + (size_t)(t + 1) * 128 * QKV3;
            uint32_t kd = kBase + (uint32_t)ns * 128 * QP * 4;
            uint32_t vd = vBase + (uint32_t)ns * 128 * VP * 4;
            #pragma unroll
            for (int i = 0; i < 8; i++) {
                int idx = tid + i * 256;
                int r = idx >> 4, c = (idx & 15) * 4;
                CP_ASYNC16(kd + (uint32_t)(r * QP + c) * 4, kp + (size_t)r * QKV3 + c);
                CP_ASYNC16(vd + (uint32_t)(r * VP + c) * 4, vp + (size_t)r * QKV3 + c);
            }
            CP_COMMIT();
            CP_WAIT1();
        } else {
            CP_WAIT0();
        }
        __syncthreads();

        float acc[16][4];
        #pragma unroll
        for (int nt = 0; nt < 16; nt++)
            #pragma unroll
            for (int c = 0; c < 4; c++) acc[nt][c] = 0.0f;

        uint32_t kb = kBase + (uint32_t)st * 128 * QP * 4;
        #pragma unroll
        for (int ks = 0; ks < 8; ks++) {
            unsigned bf[16][2];
            #pragma unroll
            for (int p = 0; p < 8; p++) {
                unsigned r0, r1, r2, r3;
                ldsm4(r0, r1, r2, r3,
                      kb + (uint32_t)((rowB + p * 16) * QP + ks * 8 + kqB) * 4);
                bf[2 * p][0] = r0; bf[2 * p][1] = r1;
                bf[2 * p + 1][0] = r2; bf[2 * p + 1][1] = r3;
            }
            #pragma unroll
            for (int nt = 0; nt < 16; nt++)
                mma8(acc[nt], qf[ks], bf[nt]);
        }

        float mx0 = -1e30f, mx1 = -1e30f;
        #pragma unroll
        for (int nt = 0; nt < 16; nt++) {
            acc[nt][0] *= 0.125f; acc[nt][1] *= 0.125f;
            acc[nt][2] *= 0.125f; acc[nt][3] *= 0.125f;
            mx0 = fmaxf(mx0, fmaxf(acc[nt][0], acc[nt][1]));
            mx1 = fmaxf(mx1, fmaxf(acc[nt][2], acc[nt][3]));
        }
        mx0 = fmaxf(mx0, __shfl_xor_sync(0xffffffffu, mx0, 1));
        mx0 = fmaxf(mx0, __shfl_xor_sync(0xffffffffu, mx0, 2));
        mx1 = fmaxf(mx1, __shfl_xor_sync(0xffffffffu, mx1, 1));
        mx1 = fmaxf(mx1, __shfl_xor_sync(0xffffffffu, mx1, 2));
        float mn0 = fmaxf(m0, mx0), mn1 = fmaxf(m1, mx1);
        float a0 = __expf(m0 - mn0), a1 = __expf(m1 - mn1);
        m0 = mn0; m1 = mn1;

        float s0 = 0.0f, s1 = 0.0f;
        #pragma unroll
        for (int nt = 0; nt < 16; nt++) {
            float p0 = __expf(acc[nt][0] - mn0);
            float p1 = __expf(acc[nt][1] - mn0);
            float p2 = __expf(acc[nt][2] - mn1);
            float p3 = __expf(acc[nt][3] - mn1);
            s0 += p0 + p1; s1 += p2 + p3;
            int col = nt * 8 + 2 * li;
            *(float2*)&Pfs[prow0 * PP + col] = make_float2(f2tf(p0), f2tf(p1));
            *(float2*)&Pfs[prow1 * PP + col] = make_float2(f2tf(p2), f2tf(p3));
        }
        s0 += __shfl_xor_sync(0xffffffffu, s0, 1);
        s0 += __shfl_xor_sync(0xffffffffu, s0, 2);
        s1 += __shfl_xor_sync(0xffffffffu, s1, 1);
        s1 += __shfl_xor_sync(0xffffffffu, s1, 2);
        l0 = l0 * a0 + s0;
        l1 = l1 * a1 + s1;

        #pragma unroll
        for (int nt = 0; nt < 8; nt++) {
            O[nt][0] *= a0; O[nt][1] *= a0;
            O[nt][2] *= a1; O[nt][3] *= a1;
        }
        __syncwarp();

        uint32_t vb = vBase + (uint32_t)st * 128 * VP * 4;
        const unsigned* Pu = (const unsigned*)Pfs;
        #pragma unroll
        for (int kk = 0; kk < 16; kk++) {
            const int k0 = kk * 8;
            unsigned af[4];
            af[0] = Pu[prow0 * PP + k0 + li];
            af[1] = Pu[prow1 * PP + k0 + li];
            af[2] = Pu[prow0 * PP + k0 + li + 4];
            af[3] = Pu[prow1 * PP + k0 + li + 4];
            const unsigned* Vu = (const unsigned*)fs;
            uint32_t vw = (vb - base) >> 2;
            #pragma unroll
            for (int nt = 0; nt < 8; nt++) {
                unsigned bfr[2];
                bfr[0] = Vu[vw + (k0 + li) * VP + nt * 8 + gi];
                bfr[1] = Vu[vw + (k0 + li + 4) * VP + nt * 8 + gi];
                mma8(O[nt], af, bfr);
            }
        }
        __syncthreads();
    }

    float inv0 = 1.0f / l0, inv1 = 1.0f / l1;
    float* out0 = ctx + (size_t)(b * SEQ + q0 + w * 16 + gi) * EMB + h * HD;
    float* out1 = out0 + (size_t)8 * EMB;
    #pragma unroll
    for (int nt = 0; nt < 8; nt++) {
        int col = nt * 8 + 2 * li;
        *(float2*)(out0 + col) = make_float2(f2tf(O[nt][0] * inv0), f2tf(O[nt][1] * inv0));
        *(float2*)(out1 + col) = make_float2(f2tf(O[nt][2] * inv1), f2tf(O[nt][3] * inv1));
    }
}

// ---------------- tf32 GEMM: 3-stage ring, ONE barrier/iter, ldmatrix --------
template<int BM, int BN, int WM, int WN, bool DO_GELU, bool DO_RESID, bool RNA_OUT>
__global__ void __launch_bounds__(256) mma_gemm(
    const float* __restrict__ A, const float* __restrict__ B,
    const float* __restrict__ bias, const float* __restrict__ R,
    float* __restrict__ C, int M, int N, int K,
    int lda, int ldb, int ldc, float scale)
{
    constexpr int BK = 32, BKP = 36;
    constexpr int MT = WM / 16;
    constexpr int NT = WN / 8;
    constexpr int WARPS_N = BN / WN;
    constexpr int STAGE = (BM + BN) * BKP;

    extern __shared__ unsigned smem[];
    const uint32_t base = (uint32_t)__cvta_generic_to_shared(smem);

    const int tid  = threadIdx.x;
    const int w    = tid >> 5;
    const int lane = tid & 31;
    const int gi   = lane >> 2;
    const int li   = lane & 3;
    const int wn   = w % WARPS_N;
    const int wm   = w / WARPS_N;
    const int bm   = blockIdx.y * BM;
    const int bn   = blockIdx.x * BN;

    const int rowA = wm * WM + (lane & 15);
    const int kqA  = (lane >> 4) * 4;
    const int rowB = wn * WN + ((lane >> 4) & 1) * 8 + (lane & 7);
    const int kqB  = ((lane >> 3) & 1) * 4;

    auto load_tile = [&](int k0, int st) {
        uint32_t sA = base + (uint32_t)st * STAGE * 4;
        uint32_t sB = sA + BM * BKP * 4;
        #pragma unroll
        for (int i = 0; i < BM / 32; i++) {
            int idx = tid + i * 256;
            int r = idx >> 3, c = (idx & 7) * 4;
            CP_ASYNC16(sA + (uint32_t)(r * BKP + c) * 4,
                       A + (size_t)(bm + r) * lda + k0 + c);
        }
        #pragma unroll
        for (int i = 0; i < BN / 32; i++) {
            int idx = tid + i * 256;
            int r = idx >> 3, c = (idx & 7) * 4;
            CP_ASYNC16(sB + (uint32_t)(r * BKP + c) * 4,
                       B + (size_t)(bn + r) * ldb + k0 + c);
        }
        CP_COMMIT();
    };

    float acc[MT][NT][4];
    #pragma unroll
    for (int i = 0; i < MT; i++)
        #pragma unroll
        for (int j = 0; j < NT; j++)
            #pragma unroll
            for (int t = 0; t < 4; t++) acc[i][j][t] = 0.0f;

    const int iters = K / BK;
    load_tile(0, 0);
    load_tile(BK, 1);

    int s = 0;
    for (int it = 0; it < iters; ++it) {
        // group `it` must be complete; group `it+1` may still be in flight.
        if (it + 1 < iters) { CP_WAIT1(); } else { CP_WAIT0(); }
        __syncthreads();   // all warps done computing stage (it-1)%3 == (it+2)%3
        if (it + 2 < iters) {
            int ns = s + 2; if (ns >= 3) ns -= 3;
            load_tile((it + 2) * BK, ns);
        }

        uint32_t sA = base + (uint32_t)s * STAGE * 4;
        uint32_t sB = sA + BM * BKP * 4;

        #pragma unroll
        for (int ks = 0; ks < BK / 8; ks++) {
            const int kb = ks * 8;
            unsigned af[MT][4];
            #pragma unroll
            for (int mt = 0; mt < MT; mt++) {
                uint32_t ad = sA + (uint32_t)((rowA + mt * 16) * BKP + kb + kqA) * 4;
                ldsm4(af[mt][0], af[mt][1], af[mt][2], af[mt][3], ad);
            }
            unsigned bf[NT][2];
            #pragma unroll
            for (int p = 0; p < NT / 2; p++) {
                uint32_t ad = sB + (uint32_t)((rowB + p * 16) * BKP + kb + kqB) * 4;
                unsigned r0, r1, r2, r3;
                ldsm4(r0, r1, r2, r3, ad);
                bf[2 * p][0] = r0; bf[2 * p][1] = r1;
                bf[2 * p + 1][0] = r2; bf[2 * p + 1][1] = r3;
            }
            #pragma unroll
            for (int mt = 0; mt < MT; mt++)
                #pragma unroll
                for (int nt = 0; nt < NT; nt++)
                    mma8(acc[mt][nt], af[mt], bf[nt]);
        }
        s = (s + 1 == 3) ? 0 : s + 1;
    }

    #pragma unroll
    for (int mt = 0; mt < MT; mt++) {
        #pragma unroll
        for (int nt = 0; nt < NT; nt++) {
            int row = bm + wm * WM + mt * 16 + gi;
            int col = bn + wn * WN + nt * 8 + 2 * li;
            float bi0 = 0.0f, bi1 = 0.0f;
            if (bias) { bi0 = bias[col]; bi1 = bias[col + 1]; }
            #pragma unroll
            for (int half = 0; half < 2; half++) {
                int rr = row + half * 8;
                float v0 = acc[mt][nt][half * 2 + 0] * scale + bi0;
                float v1 = acc[mt][nt][half * 2 + 1] * scale + bi1;
                if (DO_GELU) {
                    v0 = 0.5f * v0 * (1.0f + erff(v0 * 0.70710678118654752f));
                    v1 = 0.5f * v1 * (1.0f + erff(v1 * 0.70710678118654752f));
                }
                if (DO_RESID) {
                    float2 r2 = *(const float2*)(R + (size_t)rr * ldc + col);
                    v0 += r2.x; v1 += r2.y;
                }
                if (RNA_OUT) { v0 = f2tf(v0); v1 = f2tf(v1); }
                *(float2*)(C + (size_t)rr * ldc + col) = make_float2(v0, v1);
            }
        }
    }
}

// ---------------- launch ----------------
extern "C" void kernel_launch(void* const* d_in, const int* in_sizes, int n_in,
                              void* d_out, int out_size)
{
    const float* x     = (const float*)d_in[0];
    const float* ln1_g = (const float*)d_in[1];
    const float* ln1_b = (const float*)d_in[2];
    const float* Wq    = (const float*)d_in[3];
    const float* bq    = (const float*)d_in[4];
    const float* Wk    = (const float*)d_in[5];
    const float* bk    = (const float*)d_in[6];
    const float* Wv    = (const float*)d_in[7];
    const float* bv    = (const float*)d_in[8];
    const float* Wo    = (const float*)d_in[9];
    const float* bo    = (const float*)d_in[10];
    const float* ln2_g = (const float*)d_in[11];
    const float* ln2_b = (const float*)d_in[12];
    const float* W1    = (const float*)d_in[13];
    const float* b1    = (const float*)d_in[14];
    const float* W2    = (const float*)d_in[15];
    const float* b2    = (const float*)d_in[16];
    float* out = (float*)d_out;

    float *h, *qkv, *ctx, *x1, *h2, *ff;
    float *wqkvT, *woT, *w1T, *w2T, *bqkv;
    cudaGetSymbolAddress((void**)&h,     g_h);
    cudaGetSymbolAddress((void**)&qkv,   g_qkv);
    cudaGetSymbolAddress((void**)&ctx,   g_ctx);
    cudaGetSymbolAddress((void**)&x1,    g_x1);
    cudaGetSymbolAddress((void**)&h2,    g_h2);
    cudaGetSymbolAddress((void**)&ff,    g_ff);
    cudaGetSymbolAddress((void**)&wqkvT, g_wqkvT);
    cudaGetSymbolAddress((void**)&woT,   g_woT);
    cudaGetSymbolAddress((void**)&w1T,   g_w1T);
    cudaGetSymbolAddress((void**)&w2T,   g_w2T);
    cudaGetSymbolAddress((void**)&bqkv,  g_bqkv);

    const int SM_BIG   = 3 * (128 + 128) * 36 * 4;                        // 110592
    const int SM_FLASH = (2 * 128 * QP + 2 * 128 * VP + 8 * 16 * PP) * 4; // 210944

    cudaFuncSetAttribute((const void*)mma_gemm<128,128,64,32,false,false,true>,
                         cudaFuncAttributeMaxDynamicSharedMemorySize, SM_BIG);
    cudaFuncSetAttribute((const void*)mma_gemm<128,128,64,32,false,true,false>,
                         cudaFuncAttributeMaxDynamicSharedMemorySize, SM_BIG);
    cudaFuncSetAttribute((const void*)mma_gemm<128,128,64,32,true,false,true>,
                         cudaFuncAttributeMaxDynamicSharedMemorySize, SM_BIG);
    cudaFuncSetAttribute((const void*)flash_kernel,
                         cudaFuncAttributeMaxDynamicSharedMemorySize, SM_FLASH);

    // 0. bias concat
    bias_concat<<<9, 256>>>(bq, bk, bv, bqkv);
    // 1. all weight transposes (single launch)
    transpose_all<<<dim3(96, 96, 6), 256>>>(Wq, Wk, Wv, Wo, W1, W2);
    // 2. LN1
    ln_kernel<<<NTOK, 256>>>(x, ln1_g, ln1_b, h);
    // 3. fused QKV (outputs tf32-rounded)
    mma_gemm<128,128,64,32,false,false,true><<<dim3(QKV3/128, NTOK/128), 256, SM_BIG>>>(
        h, wqkvT, bqkv, nullptr, qkv, NTOK, QKV3, EMB, EMB, EMB, QKV3, 1.0f);
    // 4. fused flash attention -> ctx (tf32-rounded)
    flash_kernel<<<dim3(SEQ/128, BATCH*HEADS), 256, SM_FLASH>>>(qkv, ctx);
    // 5. x1 = ctx @ Wo + bo + x          <-- ncu capture target
    mma_gemm<128,128,64,32,false,true,false><<<dim3(EMB/128, NTOK/128), 256, SM_BIG>>>(
        ctx, woT, bo, x, x1, NTOK, EMB, EMB, EMB, EMB, EMB, 1.0f);
    // 6. LN2
    ln_kernel<<<NTOK, 256>>>(x1, ln2_g, ln2_b, h2);
    // 7. ff = rna(gelu(h2 @ W1 + b1))
    mma_gemm<128,128,64,32,true,false,true><<<dim3(DFF/128, NTOK/128), 256, SM_BIG>>>(
        h2, w1T, b1, nullptr, ff, NTOK, DFF, EMB, EMB, EMB, DFF, 1.0f);
    // 8. out = ff @ W2 + b2 + x1
    mma_gemm<128,128,64,32,false,true,false><<<dim3(EMB/128, NTOK/128), 256, SM_BIG>>>(
        ff, w2T, b2, x1, out, NTOK, EMB, DFF, DFF, DFF, EMB, 1.0f);
}

// round 11
// speedup vs baseline: 1.0468x; 1.0468x over previous
#include <cuda_runtime.h>
#include <math.h>
#include <stdint.h>

#define EMB   768
#define DFF   3072
#define NTOK  16384
#define HEADS 12
#define HD    64
#define SEQ   1024
#define BATCH 16
#define QKV3  2304

// ---------------- scratch (no allocations allowed) ----------------
__device__ float g_h   [NTOK * EMB];
__device__ float g_qkv [NTOK * QKV3];
__device__ float g_ctx [NTOK * EMB];
__device__ float g_x1  [NTOK * EMB];
__device__ float g_h2  [NTOK * EMB];
__device__ float g_ff  [NTOK * DFF];
// pre-transposed + tf32-rounded weights
__device__ float g_wqkvT[QKV3 * EMB];
__device__ float g_woT  [EMB * EMB];
__device__ float g_w1T  [DFF * EMB];
__device__ float g_w2T  [EMB * DFF];
__device__ float g_bqkv [QKV3];

// ---------------- helpers ----------------
__device__ __forceinline__ float f2tf(float f) {
    unsigned u;
    asm("cvt.rna.tf32.f32 %0, %1;" : "=r"(u) : "f"(f));
    return __uint_as_float(u);
}

__device__ __forceinline__ void mma8(float* c, const unsigned* a, const unsigned* b) {
    asm volatile(
        "mma.sync.aligned.m16n8k8.row.col.f32.tf32.tf32.f32 "
        "{%0,%1,%2,%3}, {%4,%5,%6,%7}, {%8,%9}, {%0,%1,%2,%3};"
        : "+f"(c[0]), "+f"(c[1]), "+f"(c[2]), "+f"(c[3])
        : "r"(a[0]), "r"(a[1]), "r"(a[2]), "r"(a[3]), "r"(b[0]), "r"(b[1]));
}

__device__ __forceinline__ void ldsm4(unsigned& r0, unsigned& r1, unsigned& r2,
                                      unsigned& r3, uint32_t addr) {
    asm volatile("ldmatrix.sync.aligned.m8n8.x4.shared.b16 {%0,%1,%2,%3}, [%4];"
                 : "=r"(r0), "=r"(r1), "=r"(r2), "=r"(r3) : "r"(addr));
}

#define CP_ASYNC16(dst, src) \
    asm volatile("cp.async.cg.shared.global [%0], [%1], 16;" :: "r"(dst), "l"(src))
#define CP_COMMIT() asm volatile("cp.async.commit_group;")
#define CP_WAIT1()  asm volatile("cp.async.wait_group 1;")
#define CP_WAIT0()  asm volatile("cp.async.wait_group 0;")

// ---------------- prep: all 6 weight transposes in ONE launch ----------------
__global__ void __launch_bounds__(256) transpose_all(
    const float* __restrict__ Wq, const float* __restrict__ Wk,
    const float* __restrict__ Wv, const float* __restrict__ Wo,
    const float* __restrict__ W1, const float* __restrict__ W2)
{
    const float* src; float* dst; int K, N;
    switch (blockIdx.z) {
        case 0: src = Wq; dst = g_wqkvT;               K = EMB; N = EMB; break;
        case 1: src = Wk; dst = g_wqkvT + EMB * EMB;   K = EMB; N = EMB; break;
        case 2: src = Wv; dst = g_wqkvT + 2*EMB*EMB;   K = EMB; N = EMB; break;
        case 3: src = Wo; dst = g_woT;                 K = EMB; N = EMB; break;
        case 4: src = W1; dst = g_w1T;                 K = EMB; N = DFF; break;
        default:src = W2; dst = g_w2T;                 K = DFF; N = EMB; break;
    }
    const int n0 = blockIdx.x * 32;
    const int k0 = blockIdx.y * 32;
    if (n0 >= N || k0 >= K) return;

    __shared__ float t[32][33];
    const int tx = threadIdx.x & 31;
    const int ty = threadIdx.x >> 5;
    #pragma unroll
    for (int j = 0; j < 4; j++)
        t[ty + j * 8][tx] = src[(size_t)(k0 + ty + j * 8) * N + n0 + tx];
    __syncthreads();
    #pragma unroll
    for (int j = 0; j < 4; j++)
        dst[(size_t)(n0 + ty + j * 8) * K + k0 + tx] = f2tf(t[tx][ty + j * 8]);
}

__global__ void bias_concat(const float* bq, const float* bk, const float* bv,
                            float* out)
{
    int i = blockIdx.x * 256 + threadIdx.x;
    if (i < QKV3) {
        float v = (i < EMB) ? bq[i] : (i < 2 * EMB) ? bk[i - EMB] : bv[i - 2 * EMB];
        out[i] = v;
    }
}

// ---------------- LayerNorm: 192 threads, one float4/thread -----------------
__device__ __forceinline__ float ln_reduce(float v, float* red) {
    #pragma unroll
    for (int off = 16; off > 0; off >>= 1)
        v += __shfl_xor_sync(0xffffffffu, v, off);
    int w = threadIdx.x >> 5;
    if ((threadIdx.x & 31) == 0) red[w] = v;
    __syncthreads();
    if (threadIdx.x < 32) {
        float t = (threadIdx.x < 6) ? red[threadIdx.x] : 0.0f;
        #pragma unroll
        for (int off = 4; off > 0; off >>= 1)
            t += __shfl_xor_sync(0xffffffffu, t, off);
        if (threadIdx.x == 0) red[0] = t;
    }
    __syncthreads();
    float r = red[0];
    __syncthreads();
    return r;
}

__global__ void __launch_bounds__(192) ln_kernel(
    const float* __restrict__ x, const float* __restrict__ gw,
    const float* __restrict__ bw, float* __restrict__ out)
{
    __shared__ float red[8];
    const int row = blockIdx.x;
    const float4 v = ((const float4*)(x + (size_t)row * EMB))[threadIdx.x];

    float mu = ln_reduce(v.x + v.y + v.z + v.w, red) * (1.0f / EMB);
    float dx = v.x - mu, dy = v.y - mu, dz = v.z - mu, dw = v.w - mu;
    float var = ln_reduce(dx * dx + dy * dy + dz * dz + dw * dw, red) * (1.0f / EMB);
    float rs = rsqrtf(var + 1e-5f);

    const float4 g4 = ((const float4*)gw)[threadIdx.x];
    const float4 b4 = ((const float4*)bw)[threadIdx.x];
    float4 o;
    o.x = f2tf(dx * rs * g4.x + b4.x);
    o.y = f2tf(dy * rs * g4.y + b4.y);
    o.z = f2tf(dz * rs * g4.z + b4.z);
    o.w = f2tf(dw * rs * g4.w + b4.w);
    ((float4*)(out + (size_t)row * EMB))[threadIdx.x] = o;
}

// ---------------- fused flash attention (tf32 mma.sync) ----------------------
#define QP 68
#define VP 72
#define PP 132

__global__ void __launch_bounds__(256) flash_kernel(
    const float* __restrict__ qkv, float* __restrict__ ctx)
{
    extern __shared__ float fs[];
    const uint32_t base  = (uint32_t)__cvta_generic_to_shared(fs);
    const uint32_t kBase = base;
    const uint32_t vBase = kBase + 2u * 128 * QP * 4;
    const uint32_t pAddr = base + (uint32_t)(2 * 128 * QP + 2 * 128 * VP) * 4;
    float* Pfs = fs + 2 * 128 * QP + 2 * 128 * VP;

    const int tid  = threadIdx.x;
    const int w    = tid >> 5;
    const int lane = tid & 31;
    const int gi   = lane >> 2;
    const int li   = lane & 3;
    const int q0   = blockIdx.x * 128;
    const int z    = blockIdx.y;
    const int b    = z / HEADS, h = z % HEADS;

    const float* qptr = qkv + (size_t)(b * SEQ + q0) * QKV3 + h * HD;
    const float* kptr = qkv + (size_t)(b * SEQ) * QKV3 + EMB + h * HD;
    const float* vptr = qkv + (size_t)(b * SEQ) * QKV3 + 2 * EMB + h * HD;

    {
        uint32_t dst = vBase + 128u * VP * 4;
        #pragma unroll
        for (int i = 0; i < 8; i++) {
            int idx = tid + i * 256;
            int r = idx >> 4, c = (idx & 15) * 4;
            CP_ASYNC16(dst + (uint32_t)(r * QP + c) * 4, qptr + (size_t)r * QKV3 + c);
        }
    }
    CP_COMMIT();
    CP_WAIT0();
    __syncthreads();

    unsigned qf[8][4];
    {
        uint32_t qb = vBase + 128u * VP * 4;
        int rowA = w * 16 + (lane & 15);
        int kqA  = (lane >> 4) * 4;
        #pragma unroll
        for (int ks = 0; ks < 8; ks++)
            ldsm4(qf[ks][0], qf[ks][1], qf[ks][2], qf[ks][3],
                  qb + (uint32_t)(rowA * QP + ks * 8 + kqA) * 4);
    }
    __syncthreads();

    float m0 = -1e30f, m1 = -1e30f, l0 = 0.0f, l1 = 0.0f;
    float O[8][4];
    #pragma unroll
    for (int nt = 0; nt < 8; nt++)
        #pragma unroll
        for (int t = 0; t < 4; t++) O[nt][t] = 0.0f;

    const int rowB  = ((lane >> 4) & 1) * 8 + (lane & 7);
    const int kqB   = ((lane >> 3) & 1) * 4;
    const int prow0 = w * 16 + gi;
    const int prow1 = prow0 + 8;
    const int rowPA = w * 16 + (lane & 15);     // P A-frag ldsm rows
    const int kqPA  = (lane >> 4) * 4;

    {
        #pragma unroll
        for (int i = 0; i < 8; i++) {
            int idx = tid + i * 256;
            int r = idx >> 4, c = (idx & 15) * 4;
            CP_ASYNC16(kBase + (uint32_t)(r * QP + c) * 4, kptr + (size_t)r * QKV3 + c);
            CP_ASYNC16(vBase + (uint32_t)(r * VP + c) * 4, vptr + (size_t)r * QKV3 + c);
        }
        CP_COMMIT();
    }

    for (int t = 0; t < 8; t++) {
        const int st = t & 1;
        if (t < 7) {
            const int ns = st ^ 1;
            const float* kp = kptr + (size_t)(t + 1) * 128 * QKV3;
            const float* vp = vptr + (size_t)(t + 1) * 128 * QKV3;
            uint32_t kd = kBase + (uint32_t)ns * 128 * QP * 4;
            uint32_t vd = vBase + (uint32_t)ns * 128 * VP * 4;
            #pragma unroll
            for (int i = 0; i < 8; i++) {
                int idx = tid + i * 256;
                int r = idx >> 4, c = (idx & 15) * 4;
                CP_ASYNC16(kd + (uint32_t)(r * QP + c) * 4, kp + (size_t)r * QKV3 + c);
                CP_ASYNC16(vd + (uint32_t)(r * VP + c) * 4, vp + (size_t)r * QKV3 + c);
            }
            CP_COMMIT();
            CP_WAIT1();
        } else {
            CP_WAIT0();
        }
        __syncthreads();

        float acc[16][4];
        #pragma unroll
        for (int nt = 0; nt < 16; nt++)
            #pragma unroll
            for (int c = 0; c < 4; c++) acc[nt][c] = 0.0f;

        uint32_t kb = kBase + (uint32_t)st * 128 * QP * 4;
        #pragma unroll
        for (int ks = 0; ks < 8; ks++) {
            unsigned bf[16][2];
            #pragma unroll
            for (int p = 0; p < 8; p++) {
                unsigned r0, r1, r2, r3;
                ldsm4(r0, r1, r2, r3,
                      kb + (uint32_t)((rowB + p * 16) * QP + ks * 8 + kqB) * 4);
                bf[2 * p][0] = r0; bf[2 * p][1] = r1;
                bf[2 * p + 1][0] = r2; bf[2 * p + 1][1] = r3;
            }
            #pragma unroll
            for (int nt = 0; nt < 16; nt++)
                mma8(acc[nt], qf[ks], bf[nt]);
        }

        float mx0 = -1e30f, mx1 = -1e30f;
        #pragma unroll
        for (int nt = 0; nt < 16; nt++) {
            acc[nt][0] *= 0.125f; acc[nt][1] *= 0.125f;
            acc[nt][2] *= 0.125f; acc[nt][3] *= 0.125f;
            mx0 = fmaxf(mx0, fmaxf(acc[nt][0], acc[nt][1]));
            mx1 = fmaxf(mx1, fmaxf(acc[nt][2], acc[nt][3]));
        }
        mx0 = fmaxf(mx0, __shfl_xor_sync(0xffffffffu, mx0, 1));
        mx0 = fmaxf(mx0, __shfl_xor_sync(0xffffffffu, mx0, 2));
        mx1 = fmaxf(mx1, __shfl_xor_sync(0xffffffffu, mx1, 1));
        mx1 = fmaxf(mx1, __shfl_xor_sync(0xffffffffu, mx1, 2));
        float mn0 = fmaxf(m0, mx0), mn1 = fmaxf(m1, mx1);
        float a0 = __expf(m0 - mn0), a1 = __expf(m1 - mn1);
        m0 = mn0; m1 = mn1;

        float s0 = 0.0f, s1 = 0.0f;
        #pragma unroll
        for (int nt = 0; nt < 16; nt++) {
            float p0 = __expf(acc[nt][0] - mn0);
            float p1 = __expf(acc[nt][1] - mn0);
            float p2 = __expf(acc[nt][2] - mn1);
            float p3 = __expf(acc[nt][3] - mn1);
            s0 += p0 + p1; s1 += p2 + p3;
            int col = nt * 8 + 2 * li;
            *(float2*)&Pfs[prow0 * PP + col] = make_float2(f2tf(p0), f2tf(p1));
            *(float2*)&Pfs[prow1 * PP + col] = make_float2(f2tf(p2), f2tf(p3));
        }
        s0 += __shfl_xor_sync(0xffffffffu, s0, 1);
        s0 += __shfl_xor_sync(0xffffffffu, s0, 2);
        s1 += __shfl_xor_sync(0xffffffffu, s1, 1);
        s1 += __shfl_xor_sync(0xffffffffu, s1, 2);
        l0 = l0 * a0 + s0;
        l1 = l1 * a1 + s1;

        #pragma unroll
        for (int nt = 0; nt < 8; nt++) {
            O[nt][0] *= a0; O[nt][1] *= a0;
            O[nt][2] *= a1; O[nt][3] *= a1;
        }
        __syncwarp();

        // ---- O += P @ V : P A-frags via ldmatrix, V B-frags scalar ----
        uint32_t vb = vBase + (uint32_t)st * 128 * VP * 4;
        #pragma unroll
        for (int kk = 0; kk < 16; kk++) {
            const int k0 = kk * 8;
            unsigned af[4];
            ldsm4(af[0], af[1], af[2], af[3],
                  pAddr + (uint32_t)(rowPA * PP + k0 + kqPA) * 4);
            const unsigned* Vu = (const unsigned*)fs;
            uint32_t vw = (vb - base) >> 2;
            #pragma unroll
            for (int nt = 0; nt < 8; nt++) {
                unsigned bfr[2];
                bfr[0] = Vu[vw + (k0 + li) * VP + nt * 8 + gi];
                bfr[1] = Vu[vw + (k0 + li + 4) * VP + nt * 8 + gi];
                mma8(O[nt], af, bfr);
            }
        }
        __syncthreads();
    }

    float inv0 = 1.0f / l0, inv1 = 1.0f / l1;
    float* out0 = ctx + (size_t)(b * SEQ + q0 + w * 16 + gi) * EMB + h * HD;
    float* out1 = out0 + (size_t)8 * EMB;
    #pragma unroll
    for (int nt = 0; nt < 8; nt++) {
        int col = nt * 8 + 2 * li;
        *(float2*)(out0 + col) = make_float2(f2tf(O[nt][0] * inv0), f2tf(O[nt][1] * inv0));
        *(float2*)(out1 + col) = make_float2(f2tf(O[nt][2] * inv1), f2tf(O[nt][3] * inv1));
    }
}

// ---- tf32 GEMM: 3-stage ring, ONE barrier/iter, regs capped for 2 CTA/SM ----
template<int BM, int BN, int WM, int WN, bool DO_GELU, bool DO_RESID, bool RNA_OUT>
__global__ void __launch_bounds__(256, 2) mma_gemm(
    const float* __restrict__ A, const float* __restrict__ B,
    const float* __restrict__ bias, const float* __restrict__ R,
    float* __restrict__ C, int M, int N, int K,
    int lda, int ldb, int ldc, float scale)
{
    constexpr int BK = 32, BKP = 36;
    constexpr int MT = WM / 16;
    constexpr int NT = WN / 8;
    constexpr int WARPS_N = BN / WN;
    constexpr int STAGE = (BM + BN) * BKP;

    extern __shared__ unsigned smem[];
    const uint32_t base = (uint32_t)__cvta_generic_to_shared(smem);

    const int tid  = threadIdx.x;
    const int w    = tid >> 5;
    const int lane = tid & 31;
    const int gi   = lane >> 2;
    const int li   = lane & 3;
    const int wn   = w % WARPS_N;
    const int wm   = w / WARPS_N;
    const int bm   = blockIdx.y * BM;
    const int bn   = blockIdx.x * BN;

    const int rowA = wm * WM + (lane & 15);
    const int kqA  = (lane >> 4) * 4;
    const int rowB = wn * WN + ((lane >> 4) & 1) * 8 + (lane & 7);
    const int kqB  = ((lane >> 3) & 1) * 4;

    auto load_tile = [&](int k0, int st) {
        uint32_t sA = base + (uint32_t)st * STAGE * 4;
        uint32_t sB = sA + BM * BKP * 4;
        #pragma unroll
        for (int i = 0; i < BM / 32; i++) {
            int idx = tid + i * 256;
            int r = idx >> 3, c = (idx & 7) * 4;
            CP_ASYNC16(sA + (uint32_t)(r * BKP + c) * 4,
                       A + (size_t)(bm + r) * lda + k0 + c);
        }
        #pragma unroll
        for (int i = 0; i < BN / 32; i++) {
            int idx = tid + i * 256;
            int r = idx >> 3, c = (idx & 7) * 4;
            CP_ASYNC16(sB + (uint32_t)(r * BKP + c) * 4,
                       B + (size_t)(bn + r) * ldb + k0 + c);
        }
        CP_COMMIT();
    };

    float acc[MT][NT][4];
    #pragma unroll
    for (int i = 0; i < MT; i++)
        #pragma unroll
        for (int j = 0; j < NT; j++)
            #pragma unroll
            for (int t = 0; t < 4; t++) acc[i][j][t] = 0.0f;

    const int iters = K / BK;
    load_tile(0, 0);
    load_tile(BK, 1);

    int s = 0;
    for (int it = 0; it < iters; ++it) {
        // outstanding groups here: tiles it, it+1 -> wait leaves at most it+1
        if (it + 1 < iters) { CP_WAIT1(); } else { CP_WAIT0(); }
        __syncthreads();   // all warps done computing stage (it+2)%3 from iter it-1
        if (it + 2 < iters) {
            int ns = s + 2; if (ns >= 3) ns -= 3;
            load_tile((it + 2) * BK, ns);
        }

        uint32_t sA = base + (uint32_t)s * STAGE * 4;
        uint32_t sB = sA + BM * BKP * 4;

        #pragma unroll
        for (int ks = 0; ks < BK / 8; ks++) {
            const int kb = ks * 8;
            unsigned af[MT][4];
            #pragma unroll
            for (int mt = 0; mt < MT; mt++) {
                uint32_t ad = sA + (uint32_t)((rowA + mt * 16) * BKP + kb + kqA) * 4;
                ldsm4(af[mt][0], af[mt][1], af[mt][2], af[mt][3], ad);
            }
            unsigned bf[NT][2];
            #pragma unroll
            for (int p = 0; p < NT / 2; p++) {
                uint32_t ad = sB + (uint32_t)((rowB + p * 16) * BKP + kb + kqB) * 4;
                unsigned r0, r1, r2, r3;
                ldsm4(r0, r1, r2, r3, ad);
                bf[2 * p][0] = r0; bf[2 * p][1] = r1;
                bf[2 * p + 1][0] = r2; bf[2 * p + 1][1] = r3;
            }
            #pragma unroll
            for (int mt = 0; mt < MT; mt++)
                #pragma unroll
                for (int nt = 0; nt < NT; nt++)
                    mma8(acc[mt][nt], af[mt], bf[nt]);
        }
        s = (s + 1 == 3) ? 0 : s + 1;
    }

    #pragma unroll
    for (int mt = 0; mt < MT; mt++) {
        #pragma unroll
        for (int nt = 0; nt < NT; nt++) {
            int row = bm + wm * WM + mt * 16 + gi;
            int col = bn + wn * WN + nt * 8 + 2 * li;
            float bi0 = 0.0f, bi1 = 0.0f;
            if (bias) { bi0 = bias[col]; bi1 = bias[col + 1]; }
            #pragma unroll
            for (int half = 0; half < 2; half++) {
                int rr = row + half * 8;
                float v0 = acc[mt][nt][half * 2 + 0] * scale + bi0;
                float v1 = acc[mt][nt][half * 2 + 1] * scale + bi1;
                if (DO_GELU) {
                    v0 = 0.5f * v0 * (1.0f + erff(v0 * 0.70710678118654752f));
                    v1 = 0.5f * v1 * (1.0f + erff(v1 * 0.70710678118654752f));
                }
                if (DO_RESID) {
                    float2 r2 = *(const float2*)(R + (size_t)rr * ldc + col);
                    v0 += r2.x; v1 += r2.y;
                }
                if (RNA_OUT) { v0 = f2tf(v0); v1 = f2tf(v1); }
                *(float2*)(C + (size_t)rr * ldc + col) = make_float2(v0, v1);
            }
        }
    }
}

// ---------------- launch ----------------
extern "C" void kernel_launch(void* const* d_in, const int* in_sizes, int n_in,
                              void* d_out, int out_size)
{
    const float* x     = (const float*)d_in[0];
    const float* ln1_g = (const float*)d_in[1];
    const float* ln1_b = (const float*)d_in[2];
    const float* Wq    = (const float*)d_in[3];
    const float* bq    = (const float*)d_in[4];
    const float* Wk    = (const float*)d_in[5];
    const float* bk    = (const float*)d_in[6];
    const float* Wv    = (const float*)d_in[7];
    const float* bv    = (const float*)d_in[8];
    const float* Wo    = (const float*)d_in[9];
    const float* bo    = (const float*)d_in[10];
    const float* ln2_g = (const float*)d_in[11];
    const float* ln2_b = (const float*)d_in[12];
    const float* W1    = (const float*)d_in[13];
    const float* b1    = (const float*)d_in[14];
    const float* W2    = (const float*)d_in[15];
    const float* b2    = (const float*)d_in[16];
    float* out = (float*)d_out;

    float *h, *qkv, *ctx, *x1, *h2, *ff;
    float *wqkvT, *woT, *w1T, *w2T, *bqkv;
    cudaGetSymbolAddress((void**)&h,     g_h);
    cudaGetSymbolAddress((void**)&qkv,   g_qkv);
    cudaGetSymbolAddress((void**)&ctx,   g_ctx);
    cudaGetSymbolAddress((void**)&x1,    g_x1);
    cudaGetSymbolAddress((void**)&h2,    g_h2);
    cudaGetSymbolAddress((void**)&ff,    g_ff);
    cudaGetSymbolAddress((void**)&wqkvT, g_wqkvT);
    cudaGetSymbolAddress((void**)&woT,   g_woT);
    cudaGetSymbolAddress((void**)&w1T,   g_w1T);
    cudaGetSymbolAddress((void**)&w2T,   g_w2T);
    cudaGetSymbolAddress((void**)&bqkv,  g_bqkv);

    const int SM_BIG   = 3 * (128 + 128) * 36 * 4;                        // 110592
    const int SM_FLASH = (2 * 128 * QP + 2 * 128 * VP + 8 * 16 * PP) * 4; // 210944

    cudaFuncSetAttribute((const void*)mma_gemm<128,128,64,32,false,false,true>,
                         cudaFuncAttributeMaxDynamicSharedMemorySize, SM_BIG);
    cudaFuncSetAttribute((const void*)mma_gemm<128,128,64,32,false,true,false>,
                         cudaFuncAttributeMaxDynamicSharedMemorySize, SM_BIG);
    cudaFuncSetAttribute((const void*)mma_gemm<128,128,64,32,true,false,true>,
                         cudaFuncAttributeMaxDynamicSharedMemorySize, SM_BIG);
    cudaFuncSetAttribute((const void*)flash_kernel,
                         cudaFuncAttributeMaxDynamicSharedMemorySize, SM_FLASH);

    // 0. bias concat
    bias_concat<<<9, 256>>>(bq, bk, bv, bqkv);
    // 1. all weight transposes (single launch)
    transpose_all<<<dim3(96, 96, 6), 256>>>(Wq, Wk, Wv, Wo, W1, W2);
    // 2. LN1
    ln_kernel<<<NTOK, 192>>>(x, ln1_g, ln1_b, h);
    // 3. fused QKV (outputs tf32-rounded)
    mma_gemm<128,128,64,32,false,false,true><<<dim3(QKV3/128, NTOK/128), 256, SM_BIG>>>(
        h, wqkvT, bqkv, nullptr, qkv, NTOK, QKV3, EMB, EMB, EMB, QKV3, 1.0f);
    // 4. fused flash attention -> ctx (tf32-rounded)
    flash_kernel<<<dim3(SEQ/128, BATCH*HEADS), 256, SM_FLASH>>>(qkv, ctx);
    // 5. x1 = ctx @ Wo + bo + x          <-- ncu capture target
    mma_gemm<128,128,64,32,false,true,false><<<dim3(EMB/128, NTOK/128), 256, SM_BIG>>>(
        ctx, woT, bo, x, x1, NTOK, EMB, EMB, EMB, EMB, EMB, 1.0f);
    // 6. LN2
    ln_kernel<<<NTOK, 192>>>(x1, ln2_g, ln2_b, h2);
    // 7. ff = rna(gelu(h2 @ W1 + b1))
    mma_gemm<128,128,64,32,true,false,true><<<dim3(DFF/128, NTOK/128), 256, SM_BIG>>>(
        h2, w1T, b1, nullptr, ff, NTOK, DFF, EMB, EMB, EMB, DFF, 1.0f);
    // 8. out = ff @ W2 + b2 + x1
    mma_gemm<128,128,64,32,false,true,false><<<dim3(EMB/128, NTOK/128), 256, SM_BIG>>>(
        ff, w2T, b2, x1, out, NTOK, EMB, DFF, DFF, DFF, EMB, 1.0f);
}

// round 12
// speedup vs baseline: 1.0820x; 1.0336x over previous
#include <cuda_runtime.h>
#include <math.h>
#include <stdint.h>

#define EMB   768
#define DFF   3072
#define NTOK  16384
#define HEADS 12
#define HD    64
#define SEQ   1024
#define BATCH 16
#define QKV3  2304

// ---------------- scratch (no allocations allowed) ----------------
__device__ float g_h   [NTOK * EMB];
__device__ float g_qkv [NTOK * QKV3];
__device__ float g_ctx [NTOK * EMB];
__device__ float g_x1  [NTOK * EMB];
__device__ float g_h2  [NTOK * EMB];
__device__ float g_ff  [NTOK * DFF];
// pre-transposed + tf32-rounded weights
__device__ float g_wqkvT[QKV3 * EMB];
__device__ float g_woT  [EMB * EMB];
__device__ float g_w1T  [DFF * EMB];
__device__ float g_w2T  [EMB * DFF];
__device__ float g_bqkv [QKV3];

// ---------------- helpers ----------------
__device__ __forceinline__ float f2tf(float f) {
    unsigned u;
    asm("cvt.rna.tf32.f32 %0, %1;" : "=r"(u) : "f"(f));
    return __uint_as_float(u);
}

__device__ __forceinline__ void mma8(float* c, const unsigned* a, const unsigned* b) {
    asm volatile(
        "mma.sync.aligned.m16n8k8.row.col.f32.tf32.tf32.f32 "
        "{%0,%1,%2,%3}, {%4,%5,%6,%7}, {%8,%9}, {%0,%1,%2,%3};"
        : "+f"(c[0]), "+f"(c[1]), "+f"(c[2]), "+f"(c[3])
        : "r"(a[0]), "r"(a[1]), "r"(a[2]), "r"(a[3]), "r"(b[0]), "r"(b[1]));
}

__device__ __forceinline__ void ldsm4(unsigned& r0, unsigned& r1, unsigned& r2,
                                      unsigned& r3, uint32_t addr) {
    asm volatile("ldmatrix.sync.aligned.m8n8.x4.shared.b16 {%0,%1,%2,%3}, [%4];"
                 : "=r"(r0), "=r"(r1), "=r"(r2), "=r"(r3) : "r"(addr));
}

#define CP_ASYNC16(dst, src) \
    asm volatile("cp.async.cg.shared.global [%0], [%1], 16;" :: "r"(dst), "l"(src))
#define CP_COMMIT() asm volatile("cp.async.commit_group;")
#define CP_WAIT1()  asm volatile("cp.async.wait_group 1;")
#define CP_WAIT0()  asm volatile("cp.async.wait_group 0;")

// ---------------- prep: weight transposes (split into 2 launches) ------------
// PART=0: Wq/Wk/Wv -> g_wqkvT.  PART=1: Wo/W1/W2 -> g_woT/g_w1T/g_w2T.
template<int PART>
__global__ void __launch_bounds__(256) transpose_part(
    const float* __restrict__ Wa, const float* __restrict__ Wb,
    const float* __restrict__ Wc)
{
    const float* src; float* dst; int K, N;
    if (PART == 0) {
        switch (blockIdx.z) {
            case 0:  src = Wa; dst = g_wqkvT;             K = EMB; N = EMB; break;
            case 1:  src = Wb; dst = g_wqkvT + EMB*EMB;   K = EMB; N = EMB; break;
            default: src = Wc; dst = g_wqkvT + 2*EMB*EMB; K = EMB; N = EMB; break;
        }
    } else {
        switch (blockIdx.z) {
            case 0:  src = Wa; dst = g_woT;  K = EMB; N = EMB; break;
            case 1:  src = Wb; dst = g_w1T;  K = EMB; N = DFF; break;
            default: src = Wc; dst = g_w2T;  K = DFF; N = EMB; break;
        }
    }
    const int n0 = blockIdx.x * 32;
    const int k0 = blockIdx.y * 32;
    if (n0 >= N || k0 >= K) return;

    __shared__ float t[32][33];
    const int tx = threadIdx.x & 31;
    const int ty = threadIdx.x >> 5;
    #pragma unroll
    for (int j = 0; j < 4; j++)
        t[ty + j * 8][tx] = src[(size_t)(k0 + ty + j * 8) * N + n0 + tx];
    __syncthreads();
    #pragma unroll
    for (int j = 0; j < 4; j++)
        dst[(size_t)(n0 + ty + j * 8) * K + k0 + tx] = f2tf(t[tx][ty + j * 8]);
}

__global__ void bias_concat(const float* bq, const float* bk, const float* bv,
                            float* out)
{
    int i = blockIdx.x * 256 + threadIdx.x;
    if (i < QKV3) {
        float v = (i < EMB) ? bq[i] : (i < 2 * EMB) ? bk[i - EMB] : bv[i - 2 * EMB];
        out[i] = v;
    }
}

// ---------------- LayerNorm: 192 threads, one float4/thread -----------------
__device__ __forceinline__ float ln_reduce(float v, float* red) {
    #pragma unroll
    for (int off = 16; off > 0; off >>= 1)
        v += __shfl_xor_sync(0xffffffffu, v, off);
    int w = threadIdx.x >> 5;
    if ((threadIdx.x & 31) == 0) red[w] = v;
    __syncthreads();
    if (threadIdx.x < 32) {
        float t = (threadIdx.x < 6) ? red[threadIdx.x] : 0.0f;
        #pragma unroll
        for (int off = 4; off > 0; off >>= 1)
            t += __shfl_xor_sync(0xffffffffu, t, off);
        if (threadIdx.x == 0) red[0] = t;
    }
    __syncthreads();
    float r = red[0];
    __syncthreads();
    return r;
}

__global__ void __launch_bounds__(192) ln_kernel(
    const float* __restrict__ x, const float* __restrict__ gw,
    const float* __restrict__ bw, float* __restrict__ out)
{
    __shared__ float red[8];
    const int row = blockIdx.x;
    const float4 v = ((const float4*)(x + (size_t)row * EMB))[threadIdx.x];

    float mu = ln_reduce(v.x + v.y + v.z + v.w, red) * (1.0f / EMB);
    float dx = v.x - mu, dy = v.y - mu, dz = v.z - mu, dw = v.w - mu;
    float var = ln_reduce(dx * dx + dy * dy + dz * dz + dw * dw, red) * (1.0f / EMB);
    float rs = rsqrtf(var + 1e-5f);

    const float4 g4 = ((const float4*)gw)[threadIdx.x];
    const float4 b4 = ((const float4*)bw)[threadIdx.x];
    float4 o;
    o.x = f2tf(dx * rs * g4.x + b4.x);
    o.y = f2tf(dy * rs * g4.y + b4.y);
    o.z = f2tf(dz * rs * g4.z + b4.z);
    o.w = f2tf(dw * rs * g4.w + b4.w);
    ((float4*)(out + (size_t)row * EMB))[threadIdx.x] = o;
}

// ---------------- fused flash attention (tf32 mma.sync) ----------------------
#define QP 68
#define VP 72
#define PP 132

__global__ void __launch_bounds__(256) flash_kernel(
    const float* __restrict__ qkv, float* __restrict__ ctx)
{
    extern __shared__ float fs[];
    const uint32_t base  = (uint32_t)__cvta_generic_to_shared(fs);
    const uint32_t kBase = base;
    const uint32_t vBase = kBase + 2u * 128 * QP * 4;
    const uint32_t pAddr = base + (uint32_t)(2 * 128 * QP + 2 * 128 * VP) * 4;
    float* Pfs = fs + 2 * 128 * QP + 2 * 128 * VP;

    const int tid  = threadIdx.x;
    const int w    = tid >> 5;
    const int lane = tid & 31;
    const int gi   = lane >> 2;
    const int li   = lane & 3;
    const int q0   = blockIdx.x * 128;
    const int z    = blockIdx.y;
    const int b    = z / HEADS, h = z % HEADS;

    const float* qptr = qkv + (size_t)(b * SEQ + q0) * QKV3 + h * HD;
    const float* kptr = qkv + (size_t)(b * SEQ) * QKV3 + EMB + h * HD;
    const float* vptr = qkv + (size_t)(b * SEQ) * QKV3 + 2 * EMB + h * HD;

    {
        uint32_t dst = vBase + 128u * VP * 4;
        #pragma unroll
        for (int i = 0; i < 8; i++) {
            int idx = tid + i * 256;
            int r = idx >> 4, c = (idx & 15) * 4;
            CP_ASYNC16(dst + (uint32_t)(r * QP + c) * 4, qptr + (size_t)r * QKV3 + c);
        }
    }
    CP_COMMIT();
    CP_WAIT0();
    __syncthreads();

    unsigned qf[8][4];
    {
        uint32_t qb = vBase + 128u * VP * 4;
        int rowA = w * 16 + (lane & 15);
        int kqA  = (lane >> 4) * 4;
        #pragma unroll
        for (int ks = 0; ks < 8; ks++)
            ldsm4(qf[ks][0], qf[ks][1], qf[ks][2], qf[ks][3],
                  qb + (uint32_t)(rowA * QP + ks * 8 + kqA) * 4);
    }
    __syncthreads();

    float m0 = -1e30f, m1 = -1e30f, l0 = 0.0f, l1 = 0.0f;
    float O[8][4];
    #pragma unroll
    for (int nt = 0; nt < 8; nt++)
        #pragma unroll
        for (int t = 0; t < 4; t++) O[nt][t] = 0.0f;

    const int rowB  = ((lane >> 4) & 1) * 8 + (lane & 7);
    const int kqB   = ((lane >> 3) & 1) * 4;
    const int prow0 = w * 16 + gi;
    const int prow1 = prow0 + 8;
    const int rowPA = w * 16 + (lane & 15);
    const int kqPA  = (lane >> 4) * 4;

    {
        #pragma unroll
        for (int i = 0; i < 8; i++) {
            int idx = tid + i * 256;
            int r = idx >> 4, c = (idx & 15) * 4;
            CP_ASYNC16(kBase + (uint32_t)(r * QP + c) * 4, kptr + (size_t)r * QKV3 + c);
            CP_ASYNC16(vBase + (uint32_t)(r * VP + c) * 4, vptr + (size_t)r * QKV3 + c);
        }
        CP_COMMIT();
    }

    for (int t = 0; t < 8; t++) {
        const int st = t & 1;
        if (t < 7) {
            const int ns = st ^ 1;
            const float* kp = kptr + (size_t)(t + 1) * 128 * QKV3;
            const float* vp = vptr + (size_t)(t + 1) * 128 * QKV3;
            uint32_t kd = kBase + (uint32_t)ns * 128 * QP * 4;
            uint32_t vd = vBase + (uint32_t)ns * 128 * VP * 4;
            #pragma unroll
            for (int i = 0; i < 8; i++) {
                int idx = tid + i * 256;
                int r = idx >> 4, c = (idx & 15) * 4;
                CP_ASYNC16(kd + (uint32_t)(r * QP + c) * 4, kp + (size_t)r * QKV3 + c);
                CP_ASYNC16(vd + (uint32_t)(r * VP + c) * 4, vp + (size_t)r * QKV3 + c);
            }
            CP_COMMIT();
            CP_WAIT1();
        } else {
            CP_WAIT0();
        }
        __syncthreads();

        float acc[16][4];
        #pragma unroll
        for (int nt = 0; nt < 16; nt++)
            #pragma unroll
            for (int c = 0; c < 4; c++) acc[nt][c] = 0.0f;

        uint32_t kb = kBase + (uint32_t)st * 128 * QP * 4;
        #pragma unroll
        for (int ks = 0; ks < 8; ks++) {
            unsigned bf[16][2];
            #pragma unroll
            for (int p = 0; p < 8; p++) {
                unsigned r0, r1, r2, r3;
                ldsm4(r0, r1, r2, r3,
                      kb + (uint32_t)((rowB + p * 16) * QP + ks * 8 + kqB) * 4);
                bf[2 * p][0] = r0; bf[2 * p][1] = r1;
                bf[2 * p + 1][0] = r2; bf[2 * p + 1][1] = r3;
            }
            #pragma unroll
            for (int nt = 0; nt < 16; nt++)
                mma8(acc[nt], qf[ks], bf[nt]);
        }

        float mx0 = -1e30f, mx1 = -1e30f;
        #pragma unroll
        for (int nt = 0; nt < 16; nt++) {
            acc[nt][0] *= 0.125f; acc[nt][1] *= 0.125f;
            acc[nt][2] *= 0.125f; acc[nt][3] *= 0.125f;
            mx0 = fmaxf(mx0, fmaxf(acc[nt][0], acc[nt][1]));
            mx1 = fmaxf(mx1, fmaxf(acc[nt][2], acc[nt][3]));
        }
        mx0 = fmaxf(mx0, __shfl_xor_sync(0xffffffffu, mx0, 1));
        mx0 = fmaxf(mx0, __shfl_xor_sync(0xffffffffu, mx0, 2));
        mx1 = fmaxf(mx1, __shfl_xor_sync(0xffffffffu, mx1, 1));
        mx1 = fmaxf(mx1, __shfl_xor_sync(0xffffffffu, mx1, 2));
        float mn0 = fmaxf(m0, mx0), mn1 = fmaxf(m1, mx1);
        float a0 = __expf(m0 - mn0), a1 = __expf(m1 - mn1);
        m0 = mn0; m1 = mn1;

        float s0 = 0.0f, s1 = 0.0f;
        #pragma unroll
        for (int nt = 0; nt < 16; nt++) {
            float p0 = __expf(acc[nt][0] - mn0);
            float p1 = __expf(acc[nt][1] - mn0);
            float p2 = __expf(acc[nt][2] - mn1);
            float p3 = __expf(acc[nt][3] - mn1);
            s0 += p0 + p1; s1 += p2 + p3;
            int col = nt * 8 + 2 * li;
            *(float2*)&Pfs[prow0 * PP + col] = make_float2(f2tf(p0), f2tf(p1));
            *(float2*)&Pfs[prow1 * PP + col] = make_float2(f2tf(p2), f2tf(p3));
        }
        s0 += __shfl_xor_sync(0xffffffffu, s0, 1);
        s0 += __shfl_xor_sync(0xffffffffu, s0, 2);
        s1 += __shfl_xor_sync(0xffffffffu, s1, 1);
        s1 += __shfl_xor_sync(0xffffffffu, s1, 2);
        l0 = l0 * a0 + s0;
        l1 = l1 * a1 + s1;

        #pragma unroll
        for (int nt = 0; nt < 8; nt++) {
            O[nt][0] *= a0; O[nt][1] *= a0;
            O[nt][2] *= a1; O[nt][3] *= a1;
        }
        __syncwarp();

        // ---- O += P @ V : P A-frags via ldmatrix, V B-frags scalar ----
        uint32_t vb = vBase + (uint32_t)st * 128 * VP * 4;
        #pragma unroll
        for (int kk = 0; kk < 16; kk++) {
            const int k0 = kk * 8;
            unsigned af[4];
            ldsm4(af[0], af[1], af[2], af[3],
                  pAddr + (uint32_t)(rowPA * PP + k0 + kqPA) * 4);
            const unsigned* Vu = (const unsigned*)fs;
            uint32_t vw = (vb - base) >> 2;
            #pragma unroll
            for (int nt = 0; nt < 8; nt++) {
                unsigned bfr[2];
                bfr[0] = Vu[vw + (k0 + li) * VP + nt * 8 + gi];
                bfr[1] = Vu[vw + (k0 + li + 4) * VP + nt * 8 + gi];
                mma8(O[nt], af, bfr);
            }
        }
        __syncthreads();
    }

    float inv0 = 1.0f / l0, inv1 = 1.0f / l1;
    float* out0 = ctx + (size_t)(b * SEQ + q0 + w * 16 + gi) * EMB + h * HD;
    float* out1 = out0 + (size_t)8 * EMB;
    #pragma unroll
    for (int nt = 0; nt < 8; nt++) {
        int col = nt * 8 + 2 * li;
        *(float2*)(out0 + col) = make_float2(f2tf(O[nt][0] * inv0), f2tf(O[nt][1] * inv0));
        *(float2*)(out1 + col) = make_float2(f2tf(O[nt][2] * inv1), f2tf(O[nt][3] * inv1));
    }
}

// ---------------- tf32 GEMM: R4 winner, byte-identical (2-stage, BK=32) ------
template<int BM, int BN, int WM, int WN, bool DO_GELU, bool DO_RESID, bool RNA_OUT>
__global__ void __launch_bounds__(256) mma_gemm(
    const float* __restrict__ A, const float* __restrict__ B,
    const float* __restrict__ bias, const float* __restrict__ R,
    float* __restrict__ C, int M, int N, int K,
    int lda, int ldb, int ldc, float scale)
{
    constexpr int BK = 32, BKP = 36;
    constexpr int MT = WM / 16;
    constexpr int NT = WN / 8;
    constexpr int WARPS_N = BN / WN;
    constexpr int STAGE = (BM + BN) * BKP;

    extern __shared__ unsigned smem[];
    const uint32_t base = (uint32_t)__cvta_generic_to_shared(smem);

    const int tid  = threadIdx.x;
    const int w    = tid >> 5;
    const int lane = tid & 31;
    const int gi   = lane >> 2;
    const int li   = lane & 3;
    const int wn   = w % WARPS_N;
    const int wm   = w / WARPS_N;
    const int bm   = blockIdx.y * BM;
    const int bn   = blockIdx.x * BN;

    const int rowA = wm * WM + (lane & 15);
    const int kqA  = (lane >> 4) * 4;
    const int rowB = wn * WN + ((lane >> 4) & 1) * 8 + (lane & 7);
    const int kqB  = ((lane >> 3) & 1) * 4;

    auto load_tile = [&](int k0, int st) {
        uint32_t sA = base + (uint32_t)st * STAGE * 4;
        uint32_t sB = sA + BM * BKP * 4;
        #pragma unroll
        for (int i = 0; i < BM / 32; i++) {
            int idx = tid + i * 256;
            int r = idx >> 3, c = (idx & 7) * 4;
            CP_ASYNC16(sA + (uint32_t)(r * BKP + c) * 4,
                       A + (size_t)(bm + r) * lda + k0 + c);
        }
        #pragma unroll
        for (int i = 0; i < BN / 32; i++) {
            int idx = tid + i * 256;
            int r = idx >> 3, c = (idx & 7) * 4;
            CP_ASYNC16(sB + (uint32_t)(r * BKP + c) * 4,
                       B + (size_t)(bn + r) * ldb + k0 + c);
        }
    };

    float acc[MT][NT][4];
    #pragma unroll
    for (int i = 0; i < MT; i++)
        #pragma unroll
        for (int j = 0; j < NT; j++)
            #pragma unroll
            for (int t = 0; t < 4; t++) acc[i][j][t] = 0.0f;

    const int iters = K / BK;
    load_tile(0, 0);
    CP_COMMIT();

    for (int it = 0; it < iters; ++it) {
        const int st = it & 1;
        if (it + 1 < iters) load_tile((it + 1) * BK, st ^ 1);
        CP_COMMIT();
        CP_WAIT1();
        __syncthreads();

        uint32_t sA = base + (uint32_t)st * STAGE * 4;
        uint32_t sB = sA + BM * BKP * 4;

        #pragma unroll
        for (int ks = 0; ks < BK / 8; ks++) {
            const int kb = ks * 8;
            unsigned af[MT][4];
            #pragma unroll
            for (int mt = 0; mt < MT; mt++) {
                uint32_t ad = sA + (uint32_t)((rowA + mt * 16) * BKP + kb + kqA) * 4;
                ldsm4(af[mt][0], af[mt][1], af[mt][2], af[mt][3], ad);
            }
            unsigned bf[NT][2];
            #pragma unroll
            for (int p = 0; p < NT / 2; p++) {
                uint32_t ad = sB + (uint32_t)((rowB + p * 16) * BKP + kb + kqB) * 4;
                unsigned r0, r1, r2, r3;
                ldsm4(r0, r1, r2, r3, ad);
                bf[2 * p][0] = r0; bf[2 * p][1] = r1;
                bf[2 * p + 1][0] = r2; bf[2 * p + 1][1] = r3;
            }
            #pragma unroll
            for (int mt = 0; mt < MT; mt++)
                #pragma unroll
                for (int nt = 0; nt < NT; nt++)
                    mma8(acc[mt][nt], af[mt], bf[nt]);
        }
        __syncthreads();
    }

    #pragma unroll
    for (int mt = 0; mt < MT; mt++) {
        #pragma unroll
        for (int nt = 0; nt < NT; nt++) {
            int row = bm + wm * WM + mt * 16 + gi;
            int col = bn + wn * WN + nt * 8 + 2 * li;
            float bi0 = 0.0f, bi1 = 0.0f;
            if (bias) { bi0 = bias[col]; bi1 = bias[col + 1]; }
            #pragma unroll
            for (int half = 0; half < 2; half++) {
                int rr = row + half * 8;
                float v0 = acc[mt][nt][half * 2 + 0] * scale + bi0;
                float v1 = acc[mt][nt][half * 2 + 1] * scale + bi1;
                if (DO_GELU) {
                    v0 = 0.5f * v0 * (1.0f + erff(v0 * 0.70710678118654752f));
                    v1 = 0.5f * v1 * (1.0f + erff(v1 * 0.70710678118654752f));
                }
                if (DO_RESID) {
                    float2 r2 = *(const float2*)(R + (size_t)rr * ldc + col);
                    v0 += r2.x; v1 += r2.y;
                }
                if (RNA_OUT) { v0 = f2tf(v0); v1 = f2tf(v1); }
                *(float2*)(C + (size_t)rr * ldc + col) = make_float2(v0, v1);
            }
        }
    }
}

// ---------------- launch ----------------
extern "C" void kernel_launch(void* const* d_in, const int* in_sizes, int n_in,
                              void* d_out, int out_size)
{
    const float* x     = (const float*)d_in[0];
    const float* ln1_g = (const float*)d_in[1];
    const float* ln1_b = (const float*)d_in[2];
    const float* Wq    = (const float*)d_in[3];
    const float* bq    = (const float*)d_in[4];
    const float* Wk    = (const float*)d_in[5];
    const float* bk    = (const float*)d_in[6];
    const float* Wv    = (const float*)d_in[7];
    const float* bv    = (const float*)d_in[8];
    const float* Wo    = (const float*)d_in[9];
    const float* bo    = (const float*)d_in[10];
    const float* ln2_g = (const float*)d_in[11];
    const float* ln2_b = (const float*)d_in[12];
    const float* W1    = (const float*)d_in[13];
    const float* b1    = (const float*)d_in[14];
    const float* W2    = (const float*)d_in[15];
    const float* b2    = (const float*)d_in[16];
    float* out = (float*)d_out;

    float *h, *qkv, *ctx, *x1, *h2, *ff;
    float *wqkvT, *woT, *w1T, *w2T, *bqkv;
    cudaGetSymbolAddress((void**)&h,     g_h);
    cudaGetSymbolAddress((void**)&qkv,   g_qkv);
    cudaGetSymbolAddress((void**)&ctx,   g_ctx);
    cudaGetSymbolAddress((void**)&x1,    g_x1);
    cudaGetSymbolAddress((void**)&h2,    g_h2);
    cudaGetSymbolAddress((void**)&ff,    g_ff);
    cudaGetSymbolAddress((void**)&wqkvT, g_wqkvT);
    cudaGetSymbolAddress((void**)&woT,   g_woT);
    cudaGetSymbolAddress((void**)&w1T,   g_w1T);
    cudaGetSymbolAddress((void**)&w2T,   g_w2T);
    cudaGetSymbolAddress((void**)&bqkv,  g_bqkv);

    const int SM_BIG   = 2 * (128 + 128) * 36 * 4;                        // 73728
    const int SM_FLASH = (2 * 128 * QP + 2 * 128 * VP + 8 * 16 * PP) * 4; // 210944

    cudaFuncSetAttribute((const void*)mma_gemm<128,128,64,32,false,false,true>,
                         cudaFuncAttributeMaxDynamicSharedMemorySize, SM_BIG);
    cudaFuncSetAttribute((const void*)mma_gemm<128,128,64,32,false,true,false>,
                         cudaFuncAttributeMaxDynamicSharedMemorySize, SM_BIG);
    cudaFuncSetAttribute((const void*)mma_gemm<128,128,64,32,true,false,true>,
                         cudaFuncAttributeMaxDynamicSharedMemorySize, SM_BIG);
    cudaFuncSetAttribute((const void*)flash_kernel,
                         cudaFuncAttributeMaxDynamicSharedMemorySize, SM_FLASH);

    // Launch order: flash_kernel must land at ncu capture index 5 (-s 5 -c 1).
    // 0. QKV weight transposes
    transpose_part<0><<<dim3(96, 24, 3), 256>>>(Wq, Wk, Wv);
    // 1. bias concat
    bias_concat<<<9, 256>>>(bq, bk, bv, bqkv);
    // 2. LN1
    ln_kernel<<<NTOK, 192>>>(x, ln1_g, ln1_b, h);
    // 3. fused QKV (outputs tf32-rounded)
    mma_gemm<128,128,64,32,false,false,true><<<dim3(QKV3/128, NTOK/128), 256, SM_BIG>>>(
        h, wqkvT, bqkv, nullptr, qkv, NTOK, QKV3, EMB, EMB, EMB, QKV3, 1.0f);
    // 4. Wo/W1/W2 transposes (needed only from launch 6 on)
    transpose_part<1><<<dim3(96, 96, 3), 256>>>(Wo, W1, W2);
    // 5. fused flash attention -> ctx      <-- ncu capture target
    flash_kernel<<<dim3(SEQ/128, BATCH*HEADS), 256, SM_FLASH>>>(qkv, ctx);
    // 6. x1 = ctx @ Wo + bo + x
    mma_gemm<128,128,64,32,false,true,false><<<dim3(EMB/128, NTOK/128), 256, SM_BIG>>>(
        ctx, woT, bo, x, x1, NTOK, EMB, EMB, EMB, EMB, EMB, 1.0f);
    // 7. LN2
    ln_kernel<<<NTOK, 192>>>(x1, ln2_g, ln2_b, h2);
    // 8. ff = rna(gelu(h2 @ W1 + b1))
    mma_gemm<128,128,64,32,true,false,true><<<dim3(DFF/128, NTOK/128), 256, SM_BIG>>>(
        h2, w1T, b1, nullptr, ff, NTOK, DFF, EMB, EMB, EMB, DFF, 1.0f);
    // 9. out = ff @ W2 + b2 + x1
    mma_gemm<128,128,64,32,false,true,false><<<dim3(EMB/128, NTOK/128), 256, SM_BIG>>>(
        ff, w2T, b2, x1, out, NTOK, EMB, DFF, DFF, DFF, EMB, 1.0f);
}

// round 13
// speedup vs baseline: 1.7460x; 1.6138x over previous
#include <cuda_runtime.h>
#include <cuda_fp16.h>
#include <math.h>
#include <stdint.h>

#define EMB   768
#define DFF   3072
#define NTOK  16384
#define HEADS 12
#define HD    64
#define SEQ   1024
#define BATCH 16
#define QKV3  2304

// ---------------- scratch (no allocations allowed) ----------------
__device__ __half g_h   [NTOK * EMB];
__device__ __half g_qkv [NTOK * QKV3];
__device__ __half g_ctx [NTOK * EMB];
__device__ float  g_x1  [NTOK * EMB];
__device__ __half g_h2  [NTOK * EMB];
__device__ __half g_ff  [NTOK * DFF];
// pre-transposed + fp16 weights
__device__ __half g_wqkvT[QKV3 * EMB];
__device__ __half g_woT  [EMB * EMB];
__device__ __half g_w1T  [DFF * EMB];
__device__ __half g_w2T  [EMB * DFF];
__device__ float  g_bqkv [QKV3];

// ---------------- helpers ----------------
__device__ __forceinline__ unsigned pack2(float a, float b) {
    __half2 h = __floats2half2_rn(a, b);
    return *(unsigned*)&h;
}

__device__ __forceinline__ void mma16(float* c, const unsigned* a, const unsigned* b) {
    asm volatile(
        "mma.sync.aligned.m16n8k16.row.col.f32.f16.f16.f32 "
        "{%0,%1,%2,%3}, {%4,%5,%6,%7}, {%8,%9}, {%0,%1,%2,%3};"
        : "+f"(c[0]), "+f"(c[1]), "+f"(c[2]), "+f"(c[3])
        : "r"(a[0]), "r"(a[1]), "r"(a[2]), "r"(a[3]), "r"(b[0]), "r"(b[1]));
}

__device__ __forceinline__ void ldsm4(unsigned& r0, unsigned& r1, unsigned& r2,
                                      unsigned& r3, uint32_t addr) {
    asm volatile("ldmatrix.sync.aligned.m8n8.x4.shared.b16 {%0,%1,%2,%3}, [%4];"
                 : "=r"(r0), "=r"(r1), "=r"(r2), "=r"(r3) : "r"(addr));
}

__device__ __forceinline__ void ldsm4t(unsigned& r0, unsigned& r1, unsigned& r2,
                                       unsigned& r3, uint32_t addr) {
    asm volatile("ldmatrix.sync.aligned.m8n8.x4.trans.shared.b16 {%0,%1,%2,%3}, [%4];"
                 : "=r"(r0), "=r"(r1), "=r"(r2), "=r"(r3) : "r"(addr));
}

#define CP_ASYNC16(dst, src) \
    asm volatile("cp.async.cg.shared.global [%0], [%1], 16;" :: "r"(dst), "l"(src))
#define CP_COMMIT() asm volatile("cp.async.commit_group;")
#define CP_WAIT1()  asm volatile("cp.async.wait_group 1;")
#define CP_WAIT0()  asm volatile("cp.async.wait_group 0;")

// ---------------- prep: weight transposes (fp32 -> half, transposed) ---------
template<int PART>
__global__ void __launch_bounds__(256) transpose_part(
    const float* __restrict__ Wa, const float* __restrict__ Wb,
    const float* __restrict__ Wc)
{
    const float* src; __half* dst; int K, N;
    if (PART == 0) {
        switch (blockIdx.z) {
            case 0:  src = Wa; dst = g_wqkvT;             K = EMB; N = EMB; break;
            case 1:  src = Wb; dst = g_wqkvT + EMB*EMB;   K = EMB; N = EMB; break;
            default: src = Wc; dst = g_wqkvT + 2*EMB*EMB; K = EMB; N = EMB; break;
        }
    } else {
        switch (blockIdx.z) {
            case 0:  src = Wa; dst = g_woT;  K = EMB; N = EMB; break;
            case 1:  src = Wb; dst = g_w1T;  K = EMB; N = DFF; break;
            default: src = Wc; dst = g_w2T;  K = DFF; N = EMB; break;
        }
    }
    const int n0 = blockIdx.x * 32;
    const int k0 = blockIdx.y * 32;
    if (n0 >= N || k0 >= K) return;

    __shared__ float t[32][33];
    const int tx = threadIdx.x & 31;
    const int ty = threadIdx.x >> 5;
    #pragma unroll
    for (int j = 0; j < 4; j++)
        t[ty + j * 8][tx] = src[(size_t)(k0 + ty + j * 8) * N + n0 + tx];
    __syncthreads();
    #pragma unroll
    for (int j = 0; j < 4; j++)
        dst[(size_t)(n0 + ty + j * 8) * K + k0 + tx] = __float2half_rn(t[tx][ty + j * 8]);
}

__global__ void bias_concat(const float* bq, const float* bk, const float* bv,
                            float* out)
{
    int i = blockIdx.x * 256 + threadIdx.x;
    if (i < QKV3) {
        float v = (i < EMB) ? bq[i] : (i < 2 * EMB) ? bk[i - EMB] : bv[i - 2 * EMB];
        out[i] = v;
    }
}

// ---------------- LayerNorm: fp32 in, half out --------------------------------
__device__ __forceinline__ float ln_reduce(float v, float* red) {
    #pragma unroll
    for (int off = 16; off > 0; off >>= 1)
        v += __shfl_xor_sync(0xffffffffu, v, off);
    int w = threadIdx.x >> 5;
    if ((threadIdx.x & 31) == 0) red[w] = v;
    __syncthreads();
    if (threadIdx.x < 32) {
        float t = (threadIdx.x < 6) ? red[threadIdx.x] : 0.0f;
        #pragma unroll
        for (int off = 4; off > 0; off >>= 1)
            t += __shfl_xor_sync(0xffffffffu, t, off);
        if (threadIdx.x == 0) red[0] = t;
    }
    __syncthreads();
    float r = red[0];
    __syncthreads();
    return r;
}

__global__ void __launch_bounds__(192) ln_kernel(
    const float* __restrict__ x, const float* __restrict__ gw,
    const float* __restrict__ bw, __half* __restrict__ out)
{
    __shared__ float red[8];
    const int row = blockIdx.x;
    const float4 v = ((const float4*)(x + (size_t)row * EMB))[threadIdx.x];

    float mu = ln_reduce(v.x + v.y + v.z + v.w, red) * (1.0f / EMB);
    float dx = v.x - mu, dy = v.y - mu, dz = v.z - mu, dw = v.w - mu;
    float var = ln_reduce(dx * dx + dy * dy + dz * dz + dw * dw, red) * (1.0f / EMB);
    float rs = rsqrtf(var + 1e-5f);

    const float4 g4 = ((const float4*)gw)[threadIdx.x];
    const float4 b4 = ((const float4*)bw)[threadIdx.x];
    uint2 o;
    o.x = pack2(dx * rs * g4.x + b4.x, dy * rs * g4.y + b4.y);
    o.y = pack2(dz * rs * g4.z + b4.z, dw * rs * g4.w + b4.w);
    ((uint2*)(out + (size_t)row * EMB))[threadIdx.x] = o;
}

// ---------------- fused flash attention (fp16 mma.sync) ----------------------
#define QPh 72    // K/V/Q tile pitch in halves (16B-aligned rows, conflict-free)
#define PPh 136   // P tile pitch in halves

__global__ void __launch_bounds__(256) flash_kernel(
    const __half* __restrict__ qkv, __half* __restrict__ ctx)
{
    extern __shared__ __half fsh[];
    const uint32_t base  = (uint32_t)__cvta_generic_to_shared(fsh);
    const uint32_t kBase = base;                                 // 2*128*QPh halves
    const uint32_t vBase = kBase + 2u * 128 * QPh * 2;           // 2*128*QPh halves
    const uint32_t pAddr = vBase + 2u * 128 * QPh * 2;           // 128*PPh halves
    unsigned* Pu = (unsigned*)(fsh + 2 * 128 * QPh + 2 * 128 * QPh);

    const int tid  = threadIdx.x;
    const int w    = tid >> 5;
    const int lane = tid & 31;
    const int gi   = lane >> 2;
    const int li   = lane & 3;
    const int q0   = blockIdx.x * 128;
    const int z    = blockIdx.y;
    const int b    = z / HEADS, h = z % HEADS;

    const __half* qptr = qkv + (size_t)(b * SEQ + q0) * QKV3 + h * HD;
    const __half* kptr = qkv + (size_t)(b * SEQ) * QKV3 + EMB + h * HD;
    const __half* vptr = qkv + (size_t)(b * SEQ) * QKV3 + 2 * EMB + h * HD;

    // ---- load Q tile into V-stage-1 region ----
    {
        uint32_t dst = vBase + 128u * QPh * 2;
        #pragma unroll
        for (int i = 0; i < 4; i++) {
            int idx = tid + i * 256;
            int r = idx >> 3, c = (idx & 7) * 8;
            CP_ASYNC16(dst + (uint32_t)(r * QPh + c) * 2, qptr + (size_t)r * QKV3 + c);
        }
    }
    CP_COMMIT();
    CP_WAIT0();
    __syncthreads();

    // ---- Q fragments (4 k16-chunks over HD=64) ----
    unsigned qf[4][4];
    {
        uint32_t qb = vBase + 128u * QPh * 2;
        int rowA = w * 16 + (lane & 15);
        int kqA  = (lane >> 4) * 8;
        #pragma unroll
        for (int ks = 0; ks < 4; ks++)
            ldsm4(qf[ks][0], qf[ks][1], qf[ks][2], qf[ks][3],
                  qb + (uint32_t)(rowA * QPh + ks * 16 + kqA) * 2);
    }
    __syncthreads();

    float m0 = -1e30f, m1 = -1e30f, l0 = 0.0f, l1 = 0.0f;
    float O[8][4];
    #pragma unroll
    for (int nt = 0; nt < 8; nt++)
        #pragma unroll
        for (int t = 0; t < 4; t++) O[nt][t] = 0.0f;

    const int rowB  = lane & 15;            // B-frag row within 16-row tile
    const int kqB   = (lane >> 4) * 8;
    const int prow0 = w * 16 + gi;
    const int prow1 = prow0 + 8;
    const int rowPA = w * 16 + (lane & 15); // P A-frag rows
    const int kqPA  = (lane >> 4) * 8;

    // prime stage 0
    {
        #pragma unroll
        for (int i = 0; i < 4; i++) {
            int idx = tid + i * 256;
            int r = idx >> 3, c = (idx & 7) * 8;
            CP_ASYNC16(kBase + (uint32_t)(r * QPh + c) * 2, kptr + (size_t)r * QKV3 + c);
            CP_ASYNC16(vBase + (uint32_t)(r * QPh + c) * 2, vptr + (size_t)r * QKV3 + c);
        }
        CP_COMMIT();
    }

    for (int t = 0; t < 8; t++) {
        const int st = t & 1;
        if (t < 7) {
            const int ns = st ^ 1;
            const __half* kp = kptr + (size_t)(t + 1) * 128 * QKV3;
            const __half* vp = vptr + (size_t)(t + 1) * 128 * QKV3;
            uint32_t kd = kBase + (uint32_t)ns * 128 * QPh * 2;
            uint32_t vd = vBase + (uint32_t)ns * 128 * QPh * 2;
            #pragma unroll
            for (int i = 0; i < 4; i++) {
                int idx = tid + i * 256;
                int r = idx >> 3, c = (idx & 7) * 8;
                CP_ASYNC16(kd + (uint32_t)(r * QPh + c) * 2, kp + (size_t)r * QKV3 + c);
                CP_ASYNC16(vd + (uint32_t)(r * QPh + c) * 2, vp + (size_t)r * QKV3 + c);
            }
            CP_COMMIT();
            CP_WAIT1();
        } else {
            CP_WAIT0();
        }
        __syncthreads();

        // ---- S = Q K^T ----
        float acc[16][4];
        #pragma unroll
        for (int nt = 0; nt < 16; nt++)
            #pragma unroll
            for (int c = 0; c < 4; c++) acc[nt][c] = 0.0f;

        uint32_t kb = kBase + (uint32_t)st * 128 * QPh * 2;
        #pragma unroll
        for (int ks = 0; ks < 4; ks++) {
            const int kk = ks * 16;
            unsigned bf[16][2];
            #pragma unroll
            for (int p = 0; p < 8; p++) {
                unsigned r0, r1, r2, r3;
                ldsm4(r0, r1, r2, r3,
                      kb + (uint32_t)((p * 16 + rowB) * QPh + kk + kqB) * 2);
                bf[2 * p][0] = r0;     bf[2 * p][1] = r2;
                bf[2 * p + 1][0] = r1; bf[2 * p + 1][1] = r3;
            }
            #pragma unroll
            for (int nt = 0; nt < 16; nt++)
                mma16(acc[nt], qf[ks], bf[nt]);
        }

        // ---- online softmax (scale 1/8 folded) ----
        float mx0 = -1e30f, mx1 = -1e30f;
        #pragma unroll
        for (int nt = 0; nt < 16; nt++) {
            acc[nt][0] *= 0.125f; acc[nt][1] *= 0.125f;
            acc[nt][2] *= 0.125f; acc[nt][3] *= 0.125f;
            mx0 = fmaxf(mx0, fmaxf(acc[nt][0], acc[nt][1]));
            mx1 = fmaxf(mx1, fmaxf(acc[nt][2], acc[nt][3]));
        }
        mx0 = fmaxf(mx0, __shfl_xor_sync(0xffffffffu, mx0, 1));
        mx0 = fmaxf(mx0, __shfl_xor_sync(0xffffffffu, mx0, 2));
        mx1 = fmaxf(mx1, __shfl_xor_sync(0xffffffffu, mx1, 1));
        mx1 = fmaxf(mx1, __shfl_xor_sync(0xffffffffu, mx1, 2));
        float mn0 = fmaxf(m0, mx0), mn1 = fmaxf(m1, mx1);
        float a0 = __expf(m0 - mn0), a1 = __expf(m1 - mn1);
        m0 = mn0; m1 = mn1;

        float s0 = 0.0f, s1 = 0.0f;
        #pragma unroll
        for (int nt = 0; nt < 16; nt++) {
            float p0 = __expf(acc[nt][0] - mn0);
            float p1 = __expf(acc[nt][1] - mn0);
            float p2 = __expf(acc[nt][2] - mn1);
            float p3 = __expf(acc[nt][3] - mn1);
            s0 += p0 + p1; s1 += p2 + p3;
            int col = nt * 8 + 2 * li;
            Pu[(prow0 * PPh + col) >> 1] = pack2(p0, p1);
            Pu[(prow1 * PPh + col) >> 1] = pack2(p2, p3);
        }
        s0 += __shfl_xor_sync(0xffffffffu, s0, 1);
        s0 += __shfl_xor_sync(0xffffffffu, s0, 2);
        s1 += __shfl_xor_sync(0xffffffffu, s1, 1);
        s1 += __shfl_xor_sync(0xffffffffu, s1, 2);
        l0 = l0 * a0 + s0;
        l1 = l1 * a1 + s1;

        #pragma unroll
        for (int nt = 0; nt < 8; nt++) {
            O[nt][0] *= a0; O[nt][1] *= a0;
            O[nt][2] *= a1; O[nt][3] *= a1;
        }
        __syncwarp();

        // ---- O += P @ V : A via ldmatrix, B via ldmatrix.trans ----
        uint32_t vb = vBase + (uint32_t)st * 128 * QPh * 2;
        #pragma unroll
        for (int kk = 0; kk < 8; kk++) {
            const int k0 = kk * 16;
            unsigned af[4];
            ldsm4(af[0], af[1], af[2], af[3],
                  pAddr + (uint32_t)(rowPA * PPh + k0 + kqPA) * 2);
            #pragma unroll
            for (int np = 0; np < 4; np++) {
                unsigned r0, r1, r2, r3;
                ldsm4t(r0, r1, r2, r3,
                       vb + (uint32_t)((k0 + rowB) * QPh + np * 16 + kqB) * 2);
                unsigned b0[2] = {r0, r1};
                unsigned b1[2] = {r2, r3};
                mma16(O[2 * np],     af, b0);
                mma16(O[2 * np + 1], af, b1);
            }
        }
        __syncthreads();
    }

    // ---- epilogue: O / l -> ctx (half) ----
    float inv0 = 1.0f / l0, inv1 = 1.0f / l1;
    __half* out0 = ctx + (size_t)(b * SEQ + q0 + w * 16 + gi) * EMB + h * HD;
    __half* out1 = out0 + (size_t)8 * EMB;
    #pragma unroll
    for (int nt = 0; nt < 8; nt++) {
        int col = nt * 8 + 2 * li;
        *(unsigned*)(out0 + col) = pack2(O[nt][0] * inv0, O[nt][1] * inv0);
        *(unsigned*)(out1 + col) = pack2(O[nt][2] * inv1, O[nt][3] * inv1);
    }
}

// ---------------- fp16 GEMM: 2-stage cp.async (R4 loop shape), BK=64 ---------
// C = A[M,K] @ B[N,K]^T + bias (+gelu)(+resid); C half or float per HALF_OUT.
template<int BM, int BN, int WM, int WN, bool DO_GELU, bool DO_RESID, bool HALF_OUT>
__global__ void __launch_bounds__(256) mma_gemm(
    const __half* __restrict__ A, const __half* __restrict__ B,
    const float* __restrict__ bias, const float* __restrict__ R,
    void* __restrict__ Cv, int M, int N, int K,
    int lda, int ldb, int ldc, float scale)
{
    constexpr int BK = 64, BKP = 72;             // halves
    constexpr int MT = WM / 16;
    constexpr int NT = WN / 8;
    constexpr int WARPS_N = BN / WN;
    constexpr int STAGE = (BM + BN) * BKP;       // halves per stage

    extern __shared__ __half smemh[];
    const uint32_t base = (uint32_t)__cvta_generic_to_shared(smemh);

    const int tid  = threadIdx.x;
    const int w    = tid >> 5;
    const int lane = tid & 31;
    const int gi   = lane >> 2;
    const int li   = lane & 3;
    const int wn   = w % WARPS_N;
    const int wm   = w / WARPS_N;
    const int bm   = blockIdx.y * BM;
    const int bn   = blockIdx.x * BN;

    const int rowA = wm * WM + (lane & 15);
    const int kqA  = (lane >> 4) * 8;
    const int rowB = lane & 15;
    const int kqB  = (lane >> 4) * 8;

    auto load_tile = [&](int k0, int st) {
        uint32_t sA = base + (uint32_t)st * STAGE * 2;
        uint32_t sB = sA + BM * BKP * 2;
        #pragma unroll
        for (int i = 0; i < BM / 32; i++) {          // BM rows * 8 chunks / 256
            int idx = tid + i * 256;
            int r = idx >> 3, c = (idx & 7) * 8;
            CP_ASYNC16(sA + (uint32_t)(r * BKP + c) * 2,
                       A + (size_t)(bm + r) * lda + k0 + c);
        }
        #pragma unroll
        for (int i = 0; i < BN / 32; i++) {
            int idx = tid + i * 256;
            int r = idx >> 3, c = (idx & 7) * 8;
            CP_ASYNC16(sB + (uint32_t)(r * BKP + c) * 2,
                       B + (size_t)(bn + r) * ldb + k0 + c);
        }
    };

    float acc[MT][NT][4];
    #pragma unroll
    for (int i = 0; i < MT; i++)
        #pragma unroll
        for (int j = 0; j < NT; j++)
            #pragma unroll
            for (int t = 0; t < 4; t++) acc[i][j][t] = 0.0f;

    const int iters = K / BK;
    load_tile(0, 0);
    CP_COMMIT();

    for (int it = 0; it < iters; ++it) {
        const int st = it & 1;
        if (it + 1 < iters) load_tile((it + 1) * BK, st ^ 1);
        CP_COMMIT();
        CP_WAIT1();
        __syncthreads();

        uint32_t sA = base + (uint32_t)st * STAGE * 2;
        uint32_t sB = sA + BM * BKP * 2;

        #pragma unroll
        for (int ks = 0; ks < BK / 16; ks++) {
            const int kb = ks * 16;
            unsigned af[MT][4];
            #pragma unroll
            for (int mt = 0; mt < MT; mt++) {
                uint32_t ad = sA + (uint32_t)((rowA + mt * 16) * BKP + kb + kqA) * 2;
                ldsm4(af[mt][0], af[mt][1], af[mt][2], af[mt][3], ad);
            }
            unsigned bf[NT][2];
            #pragma unroll
            for (int p = 0; p < NT / 2; p++) {
                uint32_t ad = sB + (uint32_t)((wn * WN + p * 16 + rowB) * BKP + kb + kqB) * 2;
                unsigned r0, r1, r2, r3;
                ldsm4(r0, r1, r2, r3, ad);
                bf[2 * p][0] = r0;     bf[2 * p][1] = r2;
                bf[2 * p + 1][0] = r1; bf[2 * p + 1][1] = r3;
            }
            #pragma unroll
            for (int mt = 0; mt < MT; mt++)
                #pragma unroll
                for (int nt = 0; nt < NT; nt++)
                    mma16(acc[mt][nt], af[mt], bf[nt]);
        }
        __syncthreads();
    }

    #pragma unroll
    for (int mt = 0; mt < MT; mt++) {
        #pragma unroll
        for (int nt = 0; nt < NT; nt++) {
            int row = bm + wm * WM + mt * 16 + gi;
            int col = bn + wn * WN + nt * 8 + 2 * li;
            float bi0 = 0.0f, bi1 = 0.0f;
            if (bias) { bi0 = bias[col]; bi1 = bias[col + 1]; }
            #pragma unroll
            for (int half = 0; half < 2; half++) {
                int rr = row + half * 8;
                float v0 = acc[mt][nt][half * 2 + 0] * scale + bi0;
                float v1 = acc[mt][nt][half * 2 + 1] * scale + bi1;
                if (DO_GELU) {
                    v0 = 0.5f * v0 * (1.0f + erff(v0 * 0.70710678118654752f));
                    v1 = 0.5f * v1 * (1.0f + erff(v1 * 0.70710678118654752f));
                }
                if (DO_RESID) {
                    float2 r2 = *(const float2*)(R + (size_t)rr * ldc + col);
                    v0 += r2.x; v1 += r2.y;
                }
                if (HALF_OUT) {
                    __half* Ch = (__half*)Cv;
                    *(unsigned*)(Ch + (size_t)rr * ldc + col) = pack2(v0, v1);
                } else {
                    float* Cf = (float*)Cv;
                    *(float2*)(Cf + (size_t)rr * ldc + col) = make_float2(v0, v1);
                }
            }
        }
    }
}

// ---------------- launch ----------------
extern "C" void kernel_launch(void* const* d_in, const int* in_sizes, int n_in,
                              void* d_out, int out_size)
{
    const float* x     = (const float*)d_in[0];
    const float* ln1_g = (const float*)d_in[1];
    const float* ln1_b = (const float*)d_in[2];
    const float* Wq    = (const float*)d_in[3];
    const float* bq    = (const float*)d_in[4];
    const float* Wk    = (const float*)d_in[5];
    const float* bk    = (const float*)d_in[6];
    const float* Wv    = (const float*)d_in[7];
    const float* bv    = (const float*)d_in[8];
    const float* Wo    = (const float*)d_in[9];
    const float* bo    = (const float*)d_in[10];
    const float* ln2_g = (const float*)d_in[11];
    const float* ln2_b = (const float*)d_in[12];
    const float* W1    = (const float*)d_in[13];
    const float* b1    = (const float*)d_in[14];
    const float* W2    = (const float*)d_in[15];
    const float* b2    = (const float*)d_in[16];
    float* out = (float*)d_out;

    __half *h, *qkv, *ctx, *h2, *ff, *wqkvT, *woT, *w1T, *w2T;
    float *x1, *bqkv;
    cudaGetSymbolAddress((void**)&h,     g_h);
    cudaGetSymbolAddress((void**)&qkv,   g_qkv);
    cudaGetSymbolAddress((void**)&ctx,   g_ctx);
    cudaGetSymbolAddress((void**)&x1,    g_x1);
    cudaGetSymbolAddress((void**)&h2,    g_h2);
    cudaGetSymbolAddress((void**)&ff,    g_ff);
    cudaGetSymbolAddress((void**)&wqkvT, g_wqkvT);
    cudaGetSymbolAddress((void**)&woT,   g_woT);
    cudaGetSymbolAddress((void**)&w1T,   g_w1T);
    cudaGetSymbolAddress((void**)&w2T,   g_w2T);
    cudaGetSymbolAddress((void**)&bqkv,  g_bqkv);

    const int SM_GEMM  = 2 * (128 + 128) * 72 * 2;                 // 73728 B
    const int SM_FLASH = (4 * 128 * QPh + 128 * PPh) * 2;          // 108544 B

    cudaFuncSetAttribute((const void*)mma_gemm<128,128,64,32,false,false,true>,
                         cudaFuncAttributeMaxDynamicSharedMemorySize, SM_GEMM);
    cudaFuncSetAttribute((const void*)mma_gemm<128,128,64,32,false,true,false>,
                         cudaFuncAttributeMaxDynamicSharedMemorySize, SM_GEMM);
    cudaFuncSetAttribute((const void*)mma_gemm<128,128,64,32,true,false,true>,
                         cudaFuncAttributeMaxDynamicSharedMemorySize, SM_GEMM);
    cudaFuncSetAttribute((const void*)flash_kernel,
                         cudaFuncAttributeMaxDynamicSharedMemorySize, SM_FLASH);

    // 0. QKV weight transposes (fp32 -> half^T)
    transpose_part<0><<<dim3(96, 24, 3), 256>>>(Wq, Wk, Wv);
    // 1. bias concat
    bias_concat<<<9, 256>>>(bq, bk, bv, bqkv);
    // 2. LN1 -> half
    ln_kernel<<<NTOK, 192>>>(x, ln1_g, ln1_b, h);
    // 3. fused QKV -> half
    mma_gemm<128,128,64,32,false,false,true><<<dim3(QKV3/128, NTOK/128), 256, SM_GEMM>>>(
        h, wqkvT, bqkv, nullptr, qkv, NTOK, QKV3, EMB, EMB, EMB, QKV3, 1.0f);
    // 4. Wo/W1/W2 transposes
    transpose_part<1><<<dim3(96, 96, 3), 256>>>(Wo, W1, W2);
    // 5. fused flash attention -> ctx (half)
    flash_kernel<<<dim3(SEQ/128, BATCH*HEADS), 256, SM_FLASH>>>(qkv, ctx);
    // 6. x1 = ctx @ Wo + bo + x  (float out)
    mma_gemm<128,128,64,32,false,true,false><<<dim3(EMB/128, NTOK/128), 256, SM_GEMM>>>(
        ctx, woT, bo, x, x1, NTOK, EMB, EMB, EMB, EMB, EMB, 1.0f);
    // 7. LN2 -> half
    ln_kernel<<<NTOK, 192>>>(x1, ln2_g, ln2_b, h2);
    // 8. ff = gelu(h2 @ W1 + b1) -> half
    mma_gemm<128,128,64,32,true,false,true><<<dim3(DFF/128, NTOK/128), 256, SM_GEMM>>>(
        h2, w1T, b1, nullptr, ff, NTOK, DFF, EMB, EMB, EMB, DFF, 1.0f);
    // 9. out = ff @ W2 + b2 + x1 (float out)
    mma_gemm<128,128,64,32,false,true,false><<<dim3(EMB/128, NTOK/128), 256, SM_GEMM>>>(
        ff, w2T, b2, x1, out, NTOK, EMB, DFF, DFF, DFF, EMB, 1.0f);
}

// round 14
// speedup vs baseline: 1.7530x; 1.0040x over previous
#include <cuda_runtime.h>
#include <cuda_fp16.h>
#include <math.h>
#include <stdint.h>

#define EMB   768
#define DFF   3072
#define NTOK  16384
#define HEADS 12
#define HD    64
#define SEQ   1024
#define BATCH 16
#define QKV3  2304

// ---------------- scratch (no allocations allowed) ----------------
__device__ __half g_h   [NTOK * EMB];
__device__ __half g_qkv [NTOK * QKV3];
__device__ __half g_ctx [NTOK * EMB];
__device__ float  g_x1  [NTOK * EMB];
__device__ __half g_h2  [NTOK * EMB];
__device__ __half g_ff  [NTOK * DFF];
// pre-transposed + fp16 weights
__device__ __half g_wqkvT[QKV3 * EMB];
__device__ __half g_woT  [EMB * EMB];
__device__ __half g_w1T  [DFF * EMB];
__device__ __half g_w2T  [EMB * DFF];
__device__ float  g_bqkv [QKV3];

// ---------------- helpers ----------------
__device__ __forceinline__ unsigned pack2(float a, float b) {
    __half2 h = __floats2half2_rn(a, b);
    return *(unsigned*)&h;
}

__device__ __forceinline__ void mma16(float* c, const unsigned* a, const unsigned* b) {
    asm volatile(
        "mma.sync.aligned.m16n8k16.row.col.f32.f16.f16.f32 "
        "{%0,%1,%2,%3}, {%4,%5,%6,%7}, {%8,%9}, {%0,%1,%2,%3};"
        : "+f"(c[0]), "+f"(c[1]), "+f"(c[2]), "+f"(c[3])
        : "r"(a[0]), "r"(a[1]), "r"(a[2]), "r"(a[3]), "r"(b[0]), "r"(b[1]));
}

__device__ __forceinline__ void ldsm4(unsigned& r0, unsigned& r1, unsigned& r2,
                                      unsigned& r3, uint32_t addr) {
    asm volatile("ldmatrix.sync.aligned.m8n8.x4.shared.b16 {%0,%1,%2,%3}, [%4];"
                 : "=r"(r0), "=r"(r1), "=r"(r2), "=r"(r3) : "r"(addr));
}

__device__ __forceinline__ void ldsm4t(unsigned& r0, unsigned& r1, unsigned& r2,
                                       unsigned& r3, uint32_t addr) {
    asm volatile("ldmatrix.sync.aligned.m8n8.x4.trans.shared.b16 {%0,%1,%2,%3}, [%4];"
                 : "=r"(r0), "=r"(r1), "=r"(r2), "=r"(r3) : "r"(addr));
}

#define CP_ASYNC16(dst, src) \
    asm volatile("cp.async.cg.shared.global [%0], [%1], 16;" :: "r"(dst), "l"(src))
#define CP_COMMIT() asm volatile("cp.async.commit_group;")
#define CP_WAIT1()  asm volatile("cp.async.wait_group 1;")
#define CP_WAIT0()  asm volatile("cp.async.wait_group 0;")

// ---------------- prep: weight transposes (fp32 -> half, transposed) ---------
template<int PART>
__global__ void __launch_bounds__(256) transpose_part(
    const float* __restrict__ Wa, const float* __restrict__ Wb,
    const float* __restrict__ Wc)
{
    const float* src; __half* dst; int K, N;
    if (PART == 0) {
        switch (blockIdx.z) {
            case 0:  src = Wa; dst = g_wqkvT;             K = EMB; N = EMB; break;
            case 1:  src = Wb; dst = g_wqkvT + EMB*EMB;   K = EMB; N = EMB; break;
            default: src = Wc; dst = g_wqkvT + 2*EMB*EMB; K = EMB; N = EMB; break;
        }
    } else {
        switch (blockIdx.z) {
            case 0:  src = Wa; dst = g_woT;  K = EMB; N = EMB; break;
            case 1:  src = Wb; dst = g_w1T;  K = EMB; N = DFF; break;
            default: src = Wc; dst = g_w2T;  K = DFF; N = EMB; break;
        }
    }
    const int n0 = blockIdx.x * 32;
    const int k0 = blockIdx.y * 32;
    if (n0 >= N || k0 >= K) return;

    __shared__ float t[32][33];
    const int tx = threadIdx.x & 31;
    const int ty = threadIdx.x >> 5;
    #pragma unroll
    for (int j = 0; j < 4; j++)
        t[ty + j * 8][tx] = src[(size_t)(k0 + ty + j * 8) * N + n0 + tx];
    __syncthreads();
    #pragma unroll
    for (int j = 0; j < 4; j++)
        dst[(size_t)(n0 + ty + j * 8) * K + k0 + tx] = __float2half_rn(t[tx][ty + j * 8]);
}

__global__ void bias_concat(const float* bq, const float* bk, const float* bv,
                            float* out)
{
    int i = blockIdx.x * 256 + threadIdx.x;
    if (i < QKV3) {
        float v = (i < EMB) ? bq[i] : (i < 2 * EMB) ? bk[i - EMB] : bv[i - 2 * EMB];
        out[i] = v;
    }
}

// ---------------- LayerNorm: fp32 in, half out --------------------------------
__device__ __forceinline__ float ln_reduce(float v, float* red) {
    #pragma unroll
    for (int off = 16; off > 0; off >>= 1)
        v += __shfl_xor_sync(0xffffffffu, v, off);
    int w = threadIdx.x >> 5;
    if ((threadIdx.x & 31) == 0) red[w] = v;
    __syncthreads();
    if (threadIdx.x < 32) {
        float t = (threadIdx.x < 6) ? red[threadIdx.x] : 0.0f;
        #pragma unroll
        for (int off = 4; off > 0; off >>= 1)
            t += __shfl_xor_sync(0xffffffffu, t, off);
        if (threadIdx.x == 0) red[0] = t;
    }
    __syncthreads();
    float r = red[0];
    __syncthreads();
    return r;
}

__global__ void __launch_bounds__(192) ln_kernel(
    const float* __restrict__ x, const float* __restrict__ gw,
    const float* __restrict__ bw, __half* __restrict__ out)
{
    __shared__ float red[8];
    const int row = blockIdx.x;
    const float4 v = ((const float4*)(x + (size_t)row * EMB))[threadIdx.x];

    float mu = ln_reduce(v.x + v.y + v.z + v.w, red) * (1.0f / EMB);
    float dx = v.x - mu, dy = v.y - mu, dz = v.z - mu, dw = v.w - mu;
    float var = ln_reduce(dx * dx + dy * dy + dz * dz + dw * dw, red) * (1.0f / EMB);
    float rs = rsqrtf(var + 1e-5f);

    const float4 g4 = ((const float4*)gw)[threadIdx.x];
    const float4 b4 = ((const float4*)bw)[threadIdx.x];
    uint2 o;
    o.x = pack2(dx * rs * g4.x + b4.x, dy * rs * g4.y + b4.y);
    o.y = pack2(dz * rs * g4.z + b4.z, dw * rs * g4.w + b4.w);
    ((uint2*)(out + (size_t)row * EMB))[threadIdx.x] = o;
}

// ---------------- fused flash attention (fp16 mma.sync) ----------------------
#define QPh 72    // K/V/Q tile pitch in halves
#define PPh 136   // P tile pitch in halves

__global__ void __launch_bounds__(256) flash_kernel(
    const __half* __restrict__ qkv, __half* __restrict__ ctx)
{
    extern __shared__ __half fsh[];
    const uint32_t base  = (uint32_t)__cvta_generic_to_shared(fsh);
    const uint32_t kBase = base;
    const uint32_t vBase = kBase + 2u * 128 * QPh * 2;
    const uint32_t pAddr = vBase + 2u * 128 * QPh * 2;
    unsigned* Pu = (unsigned*)(fsh + 2 * 128 * QPh + 2 * 128 * QPh);

    const int tid  = threadIdx.x;
    const int w    = tid >> 5;
    const int lane = tid & 31;
    const int gi   = lane >> 2;
    const int li   = lane & 3;
    const int q0   = blockIdx.x * 128;
    const int z    = blockIdx.y;
    const int b    = z / HEADS, h = z % HEADS;

    const __half* qptr = qkv + (size_t)(b * SEQ + q0) * QKV3 + h * HD;
    const __half* kptr = qkv + (size_t)(b * SEQ) * QKV3 + EMB + h * HD;
    const __half* vptr = qkv + (size_t)(b * SEQ) * QKV3 + 2 * EMB + h * HD;

    {
        uint32_t dst = vBase + 128u * QPh * 2;
        #pragma unroll
        for (int i = 0; i < 4; i++) {
            int idx = tid + i * 256;
            int r = idx >> 3, c = (idx & 7) * 8;
            CP_ASYNC16(dst + (uint32_t)(r * QPh + c) * 2, qptr + (size_t)r * QKV3 + c);
        }
    }
    CP_COMMIT();
    CP_WAIT0();
    __syncthreads();

    unsigned qf[4][4];
    {
        uint32_t qb = vBase + 128u * QPh * 2;
        int rowA = w * 16 + (lane & 15);
        int kqA  = (lane >> 4) * 8;
        #pragma unroll
        for (int ks = 0; ks < 4; ks++)
            ldsm4(qf[ks][0], qf[ks][1], qf[ks][2], qf[ks][3],
                  qb + (uint32_t)(rowA * QPh + ks * 16 + kqA) * 2);
    }
    __syncthreads();

    float m0 = -1e30f, m1 = -1e30f, l0 = 0.0f, l1 = 0.0f;
    float O[8][4];
    #pragma unroll
    for (int nt = 0; nt < 8; nt++)
        #pragma unroll
        for (int t = 0; t < 4; t++) O[nt][t] = 0.0f;

    const int rowB  = lane & 15;
    const int kqB   = (lane >> 4) * 8;
    const int prow0 = w * 16 + gi;
    const int prow1 = prow0 + 8;
    const int rowPA = w * 16 + (lane & 15);
    const int kqPA  = (lane >> 4) * 8;

    {
        #pragma unroll
        for (int i = 0; i < 4; i++) {
            int idx = tid + i * 256;
            int r = idx >> 3, c = (idx & 7) * 8;
            CP_ASYNC16(kBase + (uint32_t)(r * QPh + c) * 2, kptr + (size_t)r * QKV3 + c);
            CP_ASYNC16(vBase + (uint32_t)(r * QPh + c) * 2, vptr + (size_t)r * QKV3 + c);
        }
        CP_COMMIT();
    }

    for (int t = 0; t < 8; t++) {
        const int st = t & 1;
        if (t < 7) {
            const int ns = st ^ 1;
            const __half* kp = kptr + (size_t)(t + 1) * 128 * QKV3;
            const __half* vp = vptr + (size_t)(t + 1) * 128 * QKV3;
            uint32_t kd = kBase + (uint32_t)ns * 128 * QPh * 2;
            uint32_t vd = vBase + (uint32_t)ns * 128 * QPh * 2;
            #pragma unroll
            for (int i = 0; i < 4; i++) {
                int idx = tid + i * 256;
                int r = idx >> 3, c = (idx & 7) * 8;
                CP_ASYNC16(kd + (uint32_t)(r * QPh + c) * 2, kp + (size_t)r * QKV3 + c);
                CP_ASYNC16(vd + (uint32_t)(r * QPh + c) * 2, vp + (size_t)r * QKV3 + c);
            }
            CP_COMMIT();
            CP_WAIT1();
        } else {
            CP_WAIT0();
        }
        __syncthreads();

        float acc[16][4];
        #pragma unroll
        for (int nt = 0; nt < 16; nt++)
            #pragma unroll
            for (int c = 0; c < 4; c++) acc[nt][c] = 0.0f;

        uint32_t kb = kBase + (uint32_t)st * 128 * QPh * 2;
        #pragma unroll
        for (int ks = 0; ks < 4; ks++) {
            const int kk = ks * 16;
            unsigned bf[16][2];
            #pragma unroll
            for (int p = 0; p < 8; p++) {
                unsigned r0, r1, r2, r3;
                ldsm4(r0, r1, r2, r3,
                      kb + (uint32_t)((p * 16 + rowB) * QPh + kk + kqB) * 2);
                bf[2 * p][0] = r0;     bf[2 * p][1] = r2;
                bf[2 * p + 1][0] = r1; bf[2 * p + 1][1] = r3;
            }
            #pragma unroll
            for (int nt = 0; nt < 16; nt++)
                mma16(acc[nt], qf[ks], bf[nt]);
        }

        float mx0 = -1e30f, mx1 = -1e30f;
        #pragma unroll
        for (int nt = 0; nt < 16; nt++) {
            acc[nt][0] *= 0.125f; acc[nt][1] *= 0.125f;
            acc[nt][2] *= 0.125f; acc[nt][3] *= 0.125f;
            mx0 = fmaxf(mx0, fmaxf(acc[nt][0], acc[nt][1]));
            mx1 = fmaxf(mx1, fmaxf(acc[nt][2], acc[nt][3]));
        }
        mx0 = fmaxf(mx0, __shfl_xor_sync(0xffffffffu, mx0, 1));
        mx0 = fmaxf(mx0, __shfl_xor_sync(0xffffffffu, mx0, 2));
        mx1 = fmaxf(mx1, __shfl_xor_sync(0xffffffffu, mx1, 1));
        mx1 = fmaxf(mx1, __shfl_xor_sync(0xffffffffu, mx1, 2));
        float mn0 = fmaxf(m0, mx0), mn1 = fmaxf(m1, mx1);
        float a0 = __expf(m0 - mn0), a1 = __expf(m1 - mn1);
        m0 = mn0; m1 = mn1;

        float s0 = 0.0f, s1 = 0.0f;
        #pragma unroll
        for (int nt = 0; nt < 16; nt++) {
            float p0 = __expf(acc[nt][0] - mn0);
            float p1 = __expf(acc[nt][1] - mn0);
            float p2 = __expf(acc[nt][2] - mn1);
            float p3 = __expf(acc[nt][3] - mn1);
            s0 += p0 + p1; s1 += p2 + p3;
            int col = nt * 8 + 2 * li;
            Pu[(prow0 * PPh + col) >> 1] = pack2(p0, p1);
            Pu[(prow1 * PPh + col) >> 1] = pack2(p2, p3);
        }
        s0 += __shfl_xor_sync(0xffffffffu, s0, 1);
        s0 += __shfl_xor_sync(0xffffffffu, s0, 2);
        s1 += __shfl_xor_sync(0xffffffffu, s1, 1);
        s1 += __shfl_xor_sync(0xffffffffu, s1, 2);
        l0 = l0 * a0 + s0;
        l1 = l1 * a1 + s1;

        #pragma unroll
        for (int nt = 0; nt < 8; nt++) {
            O[nt][0] *= a0; O[nt][1] *= a0;
            O[nt][2] *= a1; O[nt][3] *= a1;
        }
        __syncwarp();

        uint32_t vb = vBase + (uint32_t)st * 128 * QPh * 2;
        #pragma unroll
        for (int kk = 0; kk < 8; kk++) {
            const int k0 = kk * 16;
            unsigned af[4];
            ldsm4(af[0], af[1], af[2], af[3],
                  pAddr + (uint32_t)(rowPA * PPh + k0 + kqPA) * 2);
            #pragma unroll
            for (int np = 0; np < 4; np++) {
                unsigned r0, r1, r2, r3;
                ldsm4t(r0, r1, r2, r3,
                       vb + (uint32_t)((k0 + rowB) * QPh + np * 16 + kqB) * 2);
                unsigned b0[2] = {r0, r1};
                unsigned b1[2] = {r2, r3};
                mma16(O[2 * np],     af, b0);
                mma16(O[2 * np + 1], af, b1);
            }
        }
        __syncthreads();
    }

    float inv0 = 1.0f / l0, inv1 = 1.0f / l1;
    __half* out0 = ctx + (size_t)(b * SEQ + q0 + w * 16 + gi) * EMB + h * HD;
    __half* out1 = out0 + (size_t)8 * EMB;
    #pragma unroll
    for (int nt = 0; nt < 8; nt++) {
        int col = nt * 8 + 2 * li;
        *(unsigned*)(out0 + col) = pack2(O[nt][0] * inv0, O[nt][1] * inv0);
        *(unsigned*)(out1 + col) = pack2(O[nt][2] * inv1, O[nt][3] * inv1);
    }
}

// ---------------- fp16 GEMM: 2-stage cp.async, strength-reduced addressing ---
template<int BM, int BN, int WM, int WN, bool DO_GELU, bool DO_RESID, bool HALF_OUT>
__global__ void __launch_bounds__(256) mma_gemm(
    const __half* __restrict__ A, const __half* __restrict__ B,
    const float* __restrict__ bias, const float* __restrict__ R,
    void* __restrict__ Cv, int M, int N, int K,
    int lda, int ldb, int ldc, float scale)
{
    constexpr int BK = 64, BKP = 72;             // halves
    constexpr int MT = WM / 16;
    constexpr int NT = WN / 8;
    constexpr int WARPS_N = BN / WN;
    constexpr int STAGE = (BM + BN) * BKP;       // halves per stage
    constexpr uint32_t STAGE_B = STAGE * 2;      // bytes per stage

    extern __shared__ __half smemh[];
    const uint32_t base = (uint32_t)__cvta_generic_to_shared(smemh);

    const int tid  = threadIdx.x;
    const int w    = tid >> 5;
    const int lane = tid & 31;
    const int gi   = lane >> 2;
    const int li   = lane & 3;
    const int wn   = w % WARPS_N;
    const int wm   = w / WARPS_N;
    const int bm   = blockIdx.y * BM;
    const int bn   = blockIdx.x * BN;

    // ---- hoisted load-side addressing (advance by BK per iter) ----
    const int lrow = tid >> 3;                 // 0..31
    const int lcol = (tid & 7) * 8;            // 0..56
    const __half* Ap = A + (size_t)(bm + lrow) * lda + lcol;
    const __half* Bp = B + (size_t)(bn + lrow) * ldb + lcol;
    const size_t lda32 = (size_t)lda * 32;
    const size_t ldb32 = (size_t)ldb * 32;
    const uint32_t swA = base + (uint32_t)(lrow * BKP + lcol) * 2;
    const uint32_t swB = swA + BM * BKP * 2;

    // ---- hoisted ldsm base addresses (stage 0) ----
    const int rowA = wm * WM + (lane & 15);
    const int kqA  = (lane >> 4) * 8;
    const int rowB = lane & 15;
    const int kqB  = (lane >> 4) * 8;
    uint32_t adA0[MT], adB0[NT / 2];
    #pragma unroll
    for (int mt = 0; mt < MT; mt++)
        adA0[mt] = base + (uint32_t)((rowA + mt * 16) * BKP + kqA) * 2;
    #pragma unroll
    for (int p = 0; p < NT / 2; p++)
        adB0[p] = base + (uint32_t)(BM * BKP + (wn * WN + p * 16 + rowB) * BKP + kqB) * 2;

    float acc[MT][NT][4];
    #pragma unroll
    for (int i = 0; i < MT; i++)
        #pragma unroll
        for (int j = 0; j < NT; j++)
            #pragma unroll
            for (int t = 0; t < 4; t++) acc[i][j][t] = 0.0f;

    const int iters = K / BK;

    // prologue: stage-0 loads
    #pragma unroll
    for (int i = 0; i < BM / 32; i++)
        CP_ASYNC16(swA + (uint32_t)(i * 32 * BKP) * 2, Ap + i * lda32);
    #pragma unroll
    for (int i = 0; i < BN / 32; i++)
        CP_ASYNC16(swB + (uint32_t)(i * 32 * BKP) * 2, Bp + i * ldb32);
    CP_COMMIT();
    Ap += BK; Bp += BK;

    for (int it = 0; it < iters; ++it) {
        const uint32_t so  = (it & 1) ? STAGE_B : 0u;
        const uint32_t nso = (it & 1) ? 0u : STAGE_B;
        if (it + 1 < iters) {
            #pragma unroll
            for (int i = 0; i < BM / 32; i++)
                CP_ASYNC16(swA + nso + (uint32_t)(i * 32 * BKP) * 2, Ap + i * lda32);
            #pragma unroll
            for (int i = 0; i < BN / 32; i++)
                CP_ASYNC16(swB + nso + (uint32_t)(i * 32 * BKP) * 2, Bp + i * ldb32);
            Ap += BK; Bp += BK;
        }
        CP_COMMIT();
        CP_WAIT1();
        __syncthreads();

        #pragma unroll
        for (int ks = 0; ks < BK / 16; ks++) {
            const uint32_t kb = (uint32_t)(ks * 16) * 2;
            unsigned af[MT][4];
            #pragma unroll
            for (int mt = 0; mt < MT; mt++)
                ldsm4(af[mt][0], af[mt][1], af[mt][2], af[mt][3],
                      adA0[mt] + so + kb);
            unsigned bf[NT][2];
            #pragma unroll
            for (int p = 0; p < NT / 2; p++) {
                unsigned r0, r1, r2, r3;
                ldsm4(r0, r1, r2, r3, adB0[p] + so + kb);
                bf[2 * p][0] = r0;     bf[2 * p][1] = r2;
                bf[2 * p + 1][0] = r1; bf[2 * p + 1][1] = r3;
            }
            #pragma unroll
            for (int mt = 0; mt < MT; mt++)
                #pragma unroll
                for (int nt = 0; nt < NT; nt++)
                    mma16(acc[mt][nt], af[mt], bf[nt]);
        }
        __syncthreads();
    }

    #pragma unroll
    for (int mt = 0; mt < MT; mt++) {
        #pragma unroll
        for (int nt = 0; nt < NT; nt++) {
            int row = bm + wm * WM + mt * 16 + gi;
            int col = bn + wn * WN + nt * 8 + 2 * li;
            float bi0 = 0.0f, bi1 = 0.0f;
            if (bias) { bi0 = bias[col]; bi1 = bias[col + 1]; }
            #pragma unroll
            for (int half = 0; half < 2; half++) {
                int rr = row + half * 8;
                float v0 = acc[mt][nt][half * 2 + 0] * scale + bi0;
                float v1 = acc[mt][nt][half * 2 + 1] * scale + bi1;
                if (DO_GELU) {
                    v0 = 0.5f * v0 * (1.0f + erff(v0 * 0.70710678118654752f));
                    v1 = 0.5f * v1 * (1.0f + erff(v1 * 0.70710678118654752f));
                }
                if (DO_RESID) {
                    float2 r2 = *(const float2*)(R + (size_t)rr * ldc + col);
                    v0 += r2.x; v1 += r2.y;
                }
                if (HALF_OUT) {
                    __half* Ch = (__half*)Cv;
                    *(unsigned*)(Ch + (size_t)rr * ldc + col) = pack2(v0, v1);
                } else {
                    float* Cf = (float*)Cv;
                    *(float2*)(Cf + (size_t)rr * ldc + col) = make_float2(v0, v1);
                }
            }
        }
    }
}

// ---------------- launch ----------------
extern "C" void kernel_launch(void* const* d_in, const int* in_sizes, int n_in,
                              void* d_out, int out_size)
{
    const float* x     = (const float*)d_in[0];
    const float* ln1_g = (const float*)d_in[1];
    const float* ln1_b = (const float*)d_in[2];
    const float* Wq    = (const float*)d_in[3];
    const float* bq    = (const float*)d_in[4];
    const float* Wk    = (const float*)d_in[5];
    const float* bk    = (const float*)d_in[6];
    const float* Wv    = (const float*)d_in[7];
    const float* bv    = (const float*)d_in[8];
    const float* Wo    = (const float*)d_in[9];
    const float* bo    = (const float*)d_in[10];
    const float* ln2_g = (const float*)d_in[11];
    const float* ln2_b = (const float*)d_in[12];
    const float* W1    = (const float*)d_in[13];
    const float* b1    = (const float*)d_in[14];
    const float* W2    = (const float*)d_in[15];
    const float* b2    = (const float*)d_in[16];
    float* out = (float*)d_out;

    __half *h, *qkv, *ctx, *h2, *ff, *wqkvT, *woT, *w1T, *w2T;
    float *x1, *bqkv;
    cudaGetSymbolAddress((void**)&h,     g_h);
    cudaGetSymbolAddress((void**)&qkv,   g_qkv);
    cudaGetSymbolAddress((void**)&ctx,   g_ctx);
    cudaGetSymbolAddress((void**)&x1,    g_x1);
    cudaGetSymbolAddress((void**)&h2,    g_h2);
    cudaGetSymbolAddress((void**)&ff,    g_ff);
    cudaGetSymbolAddress((void**)&wqkvT, g_wqkvT);
    cudaGetSymbolAddress((void**)&woT,   g_woT);
    cudaGetSymbolAddress((void**)&w1T,   g_w1T);
    cudaGetSymbolAddress((void**)&w2T,   g_w2T);
    cudaGetSymbolAddress((void**)&bqkv,  g_bqkv);

    const int SM_GEMM  = 2 * (128 + 128) * 72 * 2;                 // 73728 B
    const int SM_FLASH = (4 * 128 * QPh + 128 * PPh) * 2;          // 108544 B

    cudaFuncSetAttribute((const void*)mma_gemm<128,128,64,32,false,false,true>,
                         cudaFuncAttributeMaxDynamicSharedMemorySize, SM_GEMM);
    cudaFuncSetAttribute((const void*)mma_gemm<128,128,64,32,false,true,false>,
                         cudaFuncAttributeMaxDynamicSharedMemorySize, SM_GEMM);
    cudaFuncSetAttribute((const void*)mma_gemm<128,128,64,32,true,false,true>,
                         cudaFuncAttributeMaxDynamicSharedMemorySize, SM_GEMM);
    cudaFuncSetAttribute((const void*)flash_kernel,
                         cudaFuncAttributeMaxDynamicSharedMemorySize, SM_FLASH);

    // 0. QKV weight transposes (fp32 -> half^T)
    transpose_part<0><<<dim3(96, 24, 3), 256>>>(Wq, Wk, Wv);
    // 1. bias concat
    bias_concat<<<9, 256>>>(bq, bk, bv, bqkv);
    // 2. LN1 -> half
    ln_kernel<<<NTOK, 192>>>(x, ln1_g, ln1_b, h);
    // 3. fused QKV -> half
    mma_gemm<128,128,64,32,false,false,true><<<dim3(QKV3/128, NTOK/128), 256, SM_GEMM>>>(
        h, wqkvT, bqkv, nullptr, qkv, NTOK, QKV3, EMB, EMB, EMB, QKV3, 1.0f);
    // 4. Wo/W1/W2 transposes
    transpose_part<1><<<dim3(96, 96, 3), 256>>>(Wo, W1, W2);
    // 5. fused flash attention -> ctx (half)
    flash_kernel<<<dim3(SEQ/128, BATCH*HEADS), 256, SM_FLASH>>>(qkv, ctx);
    // 6. x1 = ctx @ Wo + bo + x  (float out)
    mma_gemm<128,128,64,32,false,true,false><<<dim3(EMB/128, NTOK/128), 256, SM_GEMM>>>(
        ctx, woT, bo, x, x1, NTOK, EMB, EMB, EMB, EMB, EMB, 1.0f);
    // 7. LN2 -> half
    ln_kernel<<<NTOK, 192>>>(x1, ln2_g, ln2_b, h2);
    // 8. ff = gelu(h2 @ W1 + b1) -> half
    mma_gemm<128,128,64,32,true,false,true><<<dim3(DFF/128, NTOK/128), 256, SM_GEMM>>>(
        h2, w1T, b1, nullptr, ff, NTOK, DFF, EMB, EMB, EMB, DFF, 1.0f);
    // 9. out = ff @ W2 + b2 + x1 (float out)
    mma_gemm<128,128,64,32,false,true,false><<<dim3(EMB/128, NTOK/128), 256, SM_GEMM>>>(
        ff, w2T, b2, x1, out, NTOK, EMB, DFF, DFF, DFF, EMB, 1.0f);
}